// round 3
// baseline (speedup 1.0000x reference)
#include <cuda_runtime.h>
#include <math.h>

#define N_NODES_MAX 100000
#define N_EDGES_MAX 3200000
#define D 64
#define NL 3

// ---- device scratch (no allocation allowed). 256B-aligned for float4/red.v4. ----
__device__ __align__(256) float g_w[(size_t)NL * N_EDGES_MAX];   // per-layer edge weights
__device__ __align__(256) int   g_src[N_EDGES_MAX];
__device__ __align__(256) int   g_dst[N_EDGES_MAX];
__device__ __align__(256) float g_agg[(size_t)N_NODES_MAX * D];
__device__ __align__(256) float g_hA[(size_t)N_NODES_MAX * D];
__device__ __align__(256) float g_hB[(size_t)N_NODES_MAX * D];
__device__ int g_is64;   // 1 if edge_index buffer is int64, 0 if int32

// ---------------------------------------------------------------------------
// Kernel 0: dtype probe for edge_index. View buffer as int32 words. If the
// data is little-endian int64 with node ids < 2^31, every odd word is 0.
// Probe first 4096 words (in-bounds under BOTH interpretations: >=6.4M words).
// ---------------------------------------------------------------------------
__global__ void detect_kernel(const int* __restrict__ w32)
{
    __shared__ int any;
    if (threadIdx.x == 0) any = 0;
    __syncthreads();
    int acc = 0;
    for (int i = threadIdx.x * 2 + 1; i < 4096; i += blockDim.x * 2)
        acc |= w32[i];
    if (acc) atomicOr(&any, 1);
    __syncthreads();
    if (threadIdx.x == 0) g_is64 = (any == 0) ? 1 : 0;
}

// ---------------------------------------------------------------------------
// Kernel 1: edge prep — index convert (int64 or int32) + softplus edge
// weights for ALL 3 layers in a single pass over edge_attr.
// ---------------------------------------------------------------------------
__global__ void prep_kernel(const void* __restrict__ eidx_raw,
                            const float* __restrict__ eattr,
                            const float* __restrict__ emlp_w,   // [3][1][8]
                            const float* __restrict__ emlp_b,   // [3][1]
                            int E)
{
    int e = blockIdx.x * blockDim.x + threadIdx.x;
    if (e >= E) return;

    if (g_is64) {
        const long long* p = (const long long*)eidx_raw;
        g_src[e] = (int)p[e];
        g_dst[e] = (int)p[(size_t)E + e];
    } else {
        const int* p = (const int*)eidx_raw;
        g_src[e] = p[e];
        g_dst[e] = p[(size_t)E + e];
    }

    const float4 a0 = *(const float4*)(eattr + (size_t)e * 8);
    const float4 a1 = *(const float4*)(eattr + (size_t)e * 8 + 4);

#pragma unroll
    for (int l = 0; l < NL; l++) {
        const float* wp = emlp_w + l * 8;
        float z = emlp_b[l];
        z = fmaf(a0.x, wp[0], z);
        z = fmaf(a0.y, wp[1], z);
        z = fmaf(a0.z, wp[2], z);
        z = fmaf(a0.w, wp[3], z);
        z = fmaf(a1.x, wp[4], z);
        z = fmaf(a1.y, wp[5], z);
        z = fmaf(a1.z, wp[6], z);
        z = fmaf(a1.w, wp[7], z);
        // numerically stable softplus = max(z,0) + log1p(exp(-|z|))
        float sp = fmaxf(z, 0.f) + log1pf(expf(-fabsf(z)));
        g_w[(size_t)l * E + e] = sp;
    }
}

// ---------------------------------------------------------------------------
// Kernel 2: zero the aggregation buffer
// ---------------------------------------------------------------------------
__global__ void zero_kernel(float4* __restrict__ p, int n4)
{
    int i = blockIdx.x * blockDim.x + threadIdx.x;
    if (i < n4) p[i] = make_float4(0.f, 0.f, 0.f, 0.f);
}

// ---------------------------------------------------------------------------
// Kernel 3: scatter. 16 threads per edge, float4 lanes.
// agg[dst] += w * (h[src] - h[dst])   via red.global.add.v4.f32
// ---------------------------------------------------------------------------
__global__ void scatter_kernel(const float* __restrict__ hin,
                               float* __restrict__ agg,
                               const float* __restrict__ w,
                               const int* __restrict__ src,
                               const int* __restrict__ dst,
                               int E)
{
    long long t = (long long)blockIdx.x * blockDim.x + threadIdx.x;
    int e = (int)(t >> 4);
    int lane = (int)(t & 15);
    if (e >= E) return;

    int s = __ldg(src + e);
    int d = __ldg(dst + e);
    float we = __ldg(w + e);

    const float4 a = __ldg((const float4*)(hin + (size_t)s * D) + lane);
    const float4 b = __ldg((const float4*)(hin + (size_t)d * D) + lane);

    float mx = we * (a.x - b.x);
    float my = we * (a.y - b.y);
    float mz = we * (a.z - b.z);
    float mw = we * (a.w - b.w);

    float* p = agg + (size_t)d * D + lane * 4;
    asm volatile("red.global.add.v4.f32 [%0], {%1, %2, %3, %4};"
                 :: "l"(p), "f"(mx), "f"(my), "f"(mz), "f"(mw)
                 : "memory");
}

// ---------------------------------------------------------------------------
// Kernel 4: per-node update: h = LN(relu(agg @ W^T + b)) * gamma + beta + hin
// One warp per row; lane j computes output cols j and j+32.
// ---------------------------------------------------------------------------
__global__ void node_update_kernel(const float* __restrict__ agg,
                                   const float* __restrict__ hin,
                                   float* __restrict__ hout,
                                   const float* __restrict__ W,      // [64][64]
                                   const float* __restrict__ bias,   // [64]
                                   const float* __restrict__ gamma,  // [64]
                                   const float* __restrict__ beta,   // [64]
                                   int N)
{
    __shared__ float sW[D][D + 1];
    __shared__ float sb[D], sg[D], sbt[D];

    for (int i = threadIdx.x; i < D * D; i += blockDim.x)
        sW[i >> 6][i & 63] = W[i];
    if (threadIdx.x < D) {
        sb[threadIdx.x]  = bias[threadIdx.x];
        sg[threadIdx.x]  = gamma[threadIdx.x];
        sbt[threadIdx.x] = beta[threadIdx.x];
    }
    __syncthreads();

    const int warp = threadIdx.x >> 5;
    const int lane = threadIdx.x & 31;
    const int warps_per_grid = (blockDim.x >> 5) * gridDim.x;

    for (int r = blockIdx.x * (blockDim.x >> 5) + warp; r < N; r += warps_per_grid) {
        const float* arow = agg + (size_t)r * D;
        float a0 = arow[lane];
        float a1 = arow[lane + 32];

        float acc0 = 0.f, acc1 = 0.f;
#pragma unroll
        for (int k = 0; k < 32; k++) {
            float ak = __shfl_sync(0xffffffffu, a0, k);
            acc0 = fmaf(ak, sW[lane][k], acc0);
            acc1 = fmaf(ak, sW[lane + 32][k], acc1);
        }
#pragma unroll
        for (int k = 0; k < 32; k++) {
            float ak = __shfl_sync(0xffffffffu, a1, k);
            acc0 = fmaf(ak, sW[lane][k + 32], acc0);
            acc1 = fmaf(ak, sW[lane + 32][k + 32], acc1);
        }

        float h0 = fmaxf(acc0 + sb[lane], 0.f);
        float h1 = fmaxf(acc1 + sb[lane + 32], 0.f);

        float s  = h0 + h1;
        float sq = h0 * h0 + h1 * h1;
#pragma unroll
        for (int o = 16; o > 0; o >>= 1) {
            s  += __shfl_xor_sync(0xffffffffu, s,  o);
            sq += __shfl_xor_sync(0xffffffffu, sq, o);
        }
        float mu  = s * (1.f / D);
        float var = sq * (1.f / D) - mu * mu;
        float inv = rsqrtf(var + 1e-5f);

        hout[(size_t)r * D + lane]      = (h0 - mu) * inv * sg[lane]      + sbt[lane]      + hin[(size_t)r * D + lane];
        hout[(size_t)r * D + lane + 32] = (h1 - mu) * inv * sg[lane + 32] + sbt[lane + 32] + hin[(size_t)r * D + lane + 32];
    }
}

// ---------------------------------------------------------------------------
// Kernel 5: final projection: out = h @ fc_w^T + fc_b
// ---------------------------------------------------------------------------
__global__ void final_fc_kernel(const float* __restrict__ hin,
                                const float* __restrict__ W,     // [64][64]
                                const float* __restrict__ bias,  // [64]
                                float* __restrict__ out,
                                int N)
{
    __shared__ float sW[D][D + 1];
    __shared__ float sb[D];

    for (int i = threadIdx.x; i < D * D; i += blockDim.x)
        sW[i >> 6][i & 63] = W[i];
    if (threadIdx.x < D) sb[threadIdx.x] = bias[threadIdx.x];
    __syncthreads();

    const int warp = threadIdx.x >> 5;
    const int lane = threadIdx.x & 31;
    const int warps_per_grid = (blockDim.x >> 5) * gridDim.x;

    for (int r = blockIdx.x * (blockDim.x >> 5) + warp; r < N; r += warps_per_grid) {
        const float* hrow = hin + (size_t)r * D;
        float a0 = hrow[lane];
        float a1 = hrow[lane + 32];

        float acc0 = 0.f, acc1 = 0.f;
#pragma unroll
        for (int k = 0; k < 32; k++) {
            float ak = __shfl_sync(0xffffffffu, a0, k);
            acc0 = fmaf(ak, sW[lane][k], acc0);
            acc1 = fmaf(ak, sW[lane + 32][k], acc1);
        }
#pragma unroll
        for (int k = 0; k < 32; k++) {
            float ak = __shfl_sync(0xffffffffu, a1, k);
            acc0 = fmaf(ak, sW[lane][k + 32], acc0);
            acc1 = fmaf(ak, sW[lane + 32][k + 32], acc1);
        }

        out[(size_t)r * D + lane]      = acc0 + sb[lane];
        out[(size_t)r * D + lane + 32] = acc1 + sb[lane + 32];
    }
}

// ---------------------------------------------------------------------------
extern "C" void kernel_launch(void* const* d_in, const int* in_sizes, int n_in,
                              void* d_out, int out_size)
{
    const float* x      = (const float*)d_in[0];
    const void*  eidx   = d_in[1];                 // int64 OR int32 — probed on device
    const float* eattr  = (const float*)d_in[2];
    const float* lin_w  = (const float*)d_in[3];   // [3][64][64]
    const float* lin_b  = (const float*)d_in[4];   // [3][64]
    const float* emlp_w = (const float*)d_in[5];   // [3][1][8]
    const float* emlp_b = (const float*)d_in[6];   // [3][1]
    const float* gamma  = (const float*)d_in[7];   // [3][64]
    const float* beta   = (const float*)d_in[8];   // [3][64]
    const float* fc_w   = (const float*)d_in[9];   // [64][64]
    const float* fc_b   = (const float*)d_in[10];  // [64]
    float*       out    = (float*)d_out;

    const int E = in_sizes[1] / 2;
    const int N = in_sizes[0] / D;

    float *w_ptr, *agg, *hA, *hB;
    int   *srcp, *dstp;
    cudaGetSymbolAddress((void**)&w_ptr, g_w);
    cudaGetSymbolAddress((void**)&agg,   g_agg);
    cudaGetSymbolAddress((void**)&hA,    g_hA);
    cudaGetSymbolAddress((void**)&hB,    g_hB);
    cudaGetSymbolAddress((void**)&srcp,  g_src);
    cudaGetSymbolAddress((void**)&dstp,  g_dst);

    detect_kernel<<<1, 256>>>((const int*)eidx);
    prep_kernel<<<(E + 255) / 256, 256>>>(eidx, eattr, emlp_w, emlp_b, E);

    const int n4 = N * D / 4;
    const long long scatter_threads = (long long)E * 16;
    const int scatter_blocks = (int)((scatter_threads + 255) / 256);

    const float* hin = x;
    float* houts[NL] = { hA, hB, hA };

    for (int l = 0; l < NL; l++) {
        zero_kernel<<<(n4 + 255) / 256, 256>>>((float4*)agg, n4);
        scatter_kernel<<<scatter_blocks, 256>>>(hin, agg, w_ptr + (size_t)l * E,
                                                srcp, dstp, E);
        node_update_kernel<<<1480, 128>>>(agg, hin, houts[l],
                                          lin_w + (size_t)l * D * D,
                                          lin_b + (size_t)l * D,
                                          gamma + (size_t)l * D,
                                          beta  + (size_t)l * D,
                                          N);
        hin = houts[l];
    }

    final_fc_kernel<<<1480, 128>>>(hin, fc_w, fc_b, out, N);
}

// round 4
// speedup vs baseline: 1.0113x; 1.0113x over previous
#include <cuda_runtime.h>
#include <math.h>

#define N_NODES_MAX 100000
#define N_EDGES_MAX 3200000
#define D 64
#define NL 3

// ---- device scratch (no allocation allowed). 256B-aligned for float4/red.v4. ----
__device__ __align__(256) float g_w[(size_t)NL * N_EDGES_MAX];   // per-layer edge weights
__device__ __align__(256) float g_c[(size_t)NL * N_NODES_MAX];   // per-layer, per-node sum of w over incoming edges
__device__ __align__(256) int   g_src[N_EDGES_MAX];
__device__ __align__(256) int   g_dst[N_EDGES_MAX];
__device__ __align__(256) float g_agg[(size_t)N_NODES_MAX * D];
__device__ __align__(256) float g_hA[(size_t)N_NODES_MAX * D];
__device__ __align__(256) float g_hB[(size_t)N_NODES_MAX * D];
__device__ int g_is64;   // 1 if edge_index buffer is int64, 0 if int32

// ---------------------------------------------------------------------------
// Kernel 0: dtype probe for edge_index (int64 vs int32), same as R2.
// ---------------------------------------------------------------------------
__global__ void detect_kernel(const int* __restrict__ w32)
{
    __shared__ int any;
    if (threadIdx.x == 0) any = 0;
    __syncthreads();
    int acc = 0;
    for (int i = threadIdx.x * 2 + 1; i < 4096; i += blockDim.x * 2)
        acc |= w32[i];
    if (acc) atomicOr(&any, 1);
    __syncthreads();
    if (threadIdx.x == 0) g_is64 = (any == 0) ? 1 : 0;
}

// ---------------------------------------------------------------------------
// Kernel 0b: zero the per-node coefficient arrays (all layers at once).
// ---------------------------------------------------------------------------
__global__ void zero_c_kernel(int n)
{
    int i = blockIdx.x * blockDim.x + threadIdx.x;
    if (i < n) g_c[i] = 0.f;
}

// ---------------------------------------------------------------------------
// Kernel 1: edge prep — index convert + softplus weights for ALL 3 layers in
// one pass over edge_attr; also accumulates c[l][dst] += w (scalar RED,
// spread addresses into 400KB L2-resident arrays).
// ---------------------------------------------------------------------------
__global__ void prep_kernel(const void* __restrict__ eidx_raw,
                            const float* __restrict__ eattr,
                            const float* __restrict__ emlp_w,   // [3][1][8]
                            const float* __restrict__ emlp_b,   // [3][1]
                            int E, int N)
{
    int e = blockIdx.x * blockDim.x + threadIdx.x;
    if (e >= E) return;

    int s, d;
    if (g_is64) {
        const long long* p = (const long long*)eidx_raw;
        s = (int)p[e];
        d = (int)p[(size_t)E + e];
    } else {
        const int* p = (const int*)eidx_raw;
        s = p[e];
        d = p[(size_t)E + e];
    }
    g_src[e] = s;
    g_dst[e] = d;

    const float4 a0 = *(const float4*)(eattr + (size_t)e * 8);
    const float4 a1 = *(const float4*)(eattr + (size_t)e * 8 + 4);

#pragma unroll
    for (int l = 0; l < NL; l++) {
        const float* wp = emlp_w + l * 8;
        float z = emlp_b[l];
        z = fmaf(a0.x, wp[0], z);
        z = fmaf(a0.y, wp[1], z);
        z = fmaf(a0.z, wp[2], z);
        z = fmaf(a0.w, wp[3], z);
        z = fmaf(a1.x, wp[4], z);
        z = fmaf(a1.y, wp[5], z);
        z = fmaf(a1.z, wp[6], z);
        z = fmaf(a1.w, wp[7], z);
        // numerically stable softplus = max(z,0) + log1p(exp(-|z|))
        float sp = fmaxf(z, 0.f) + log1pf(expf(-fabsf(z)));
        g_w[(size_t)l * E + e] = sp;
        atomicAdd(&g_c[(size_t)l * N + d], sp);
    }
}

// ---------------------------------------------------------------------------
// Kernel 2: zero the aggregation buffer
// ---------------------------------------------------------------------------
__global__ void zero_kernel(float4* __restrict__ p, int n4)
{
    int i = blockIdx.x * blockDim.x + threadIdx.x;
    if (i < n4) p[i] = make_float4(0.f, 0.f, 0.f, 0.f);
}

// ---------------------------------------------------------------------------
// Kernel 3: scatter. 16 threads per edge, float4 lanes.
// agg[dst] += w * h[src]   via red.global.add.v4.f32
// (the  -(sum w)*h[dst]  correction is applied in node_update via g_c)
// ---------------------------------------------------------------------------
__global__ void scatter_kernel(const float* __restrict__ hin,
                               float* __restrict__ agg,
                               const float* __restrict__ w,
                               const int* __restrict__ src,
                               const int* __restrict__ dst,
                               int E)
{
    long long t = (long long)blockIdx.x * blockDim.x + threadIdx.x;
    int e = (int)(t >> 4);
    int lane = (int)(t & 15);
    if (e >= E) return;

    int s = __ldg(src + e);
    int d = __ldg(dst + e);
    float we = __ldg(w + e);

    const float4 a = __ldg((const float4*)(hin + (size_t)s * D) + lane);

    float mx = we * a.x;
    float my = we * a.y;
    float mz = we * a.z;
    float mw = we * a.w;

    float* p = agg + (size_t)d * D + lane * 4;
    asm volatile("red.global.add.v4.f32 [%0], {%1, %2, %3, %4};"
                 :: "l"(p), "f"(mx), "f"(my), "f"(mz), "f"(mw)
                 : "memory");
}

// ---------------------------------------------------------------------------
// Kernel 4: per-node update:
//   a = agg[r] - c[r]*hin[r]            (completes the message sum)
//   h = LN(relu(a @ W^T + b)) * gamma + beta + hin[r]
// One warp per row; lane j handles cols j and j+32.
// ---------------------------------------------------------------------------
__global__ void node_update_kernel(const float* __restrict__ agg,
                                   const float* __restrict__ hin,
                                   float* __restrict__ hout,
                                   const float* __restrict__ cvec,   // [N]
                                   const float* __restrict__ W,      // [64][64]
                                   const float* __restrict__ bias,   // [64]
                                   const float* __restrict__ gamma,  // [64]
                                   const float* __restrict__ beta,   // [64]
                                   int N)
{
    __shared__ float sW[D][D + 1];
    __shared__ float sb[D], sg[D], sbt[D];

    for (int i = threadIdx.x; i < D * D; i += blockDim.x)
        sW[i >> 6][i & 63] = W[i];
    if (threadIdx.x < D) {
        sb[threadIdx.x]  = bias[threadIdx.x];
        sg[threadIdx.x]  = gamma[threadIdx.x];
        sbt[threadIdx.x] = beta[threadIdx.x];
    }
    __syncthreads();

    const int warp = threadIdx.x >> 5;
    const int lane = threadIdx.x & 31;
    const int warps_per_grid = (blockDim.x >> 5) * gridDim.x;

    for (int r = blockIdx.x * (blockDim.x >> 5) + warp; r < N; r += warps_per_grid) {
        float hi0 = hin[(size_t)r * D + lane];
        float hi1 = hin[(size_t)r * D + lane + 32];
        float c = __ldg(cvec + r);

        float a0 = agg[(size_t)r * D + lane]      - c * hi0;
        float a1 = agg[(size_t)r * D + lane + 32] - c * hi1;

        float acc0 = 0.f, acc1 = 0.f;
#pragma unroll
        for (int k = 0; k < 32; k++) {
            float ak = __shfl_sync(0xffffffffu, a0, k);
            acc0 = fmaf(ak, sW[lane][k], acc0);
            acc1 = fmaf(ak, sW[lane + 32][k], acc1);
        }
#pragma unroll
        for (int k = 0; k < 32; k++) {
            float ak = __shfl_sync(0xffffffffu, a1, k);
            acc0 = fmaf(ak, sW[lane][k + 32], acc0);
            acc1 = fmaf(ak, sW[lane + 32][k + 32], acc1);
        }

        float h0 = fmaxf(acc0 + sb[lane], 0.f);
        float h1 = fmaxf(acc1 + sb[lane + 32], 0.f);

        float s  = h0 + h1;
        float sq = h0 * h0 + h1 * h1;
#pragma unroll
        for (int o = 16; o > 0; o >>= 1) {
            s  += __shfl_xor_sync(0xffffffffu, s,  o);
            sq += __shfl_xor_sync(0xffffffffu, sq, o);
        }
        float mu  = s * (1.f / D);
        float var = sq * (1.f / D) - mu * mu;
        float inv = rsqrtf(var + 1e-5f);

        hout[(size_t)r * D + lane]      = (h0 - mu) * inv * sg[lane]      + sbt[lane]      + hi0;
        hout[(size_t)r * D + lane + 32] = (h1 - mu) * inv * sg[lane + 32] + sbt[lane + 32] + hi1;
    }
}

// ---------------------------------------------------------------------------
// Kernel 5: FUSED last layer + final projection:
//   h3 = LN(relu((agg - c*hin) @ W^T + b)) * gamma + beta + hin
//   out = h3 @ fcW^T + fc_b
// h3 never touches global memory.
// ---------------------------------------------------------------------------
__global__ void node_update_fc_kernel(const float* __restrict__ agg,
                                      const float* __restrict__ hin,
                                      float* __restrict__ out,
                                      const float* __restrict__ cvec,
                                      const float* __restrict__ W,      // [64][64]
                                      const float* __restrict__ bias,
                                      const float* __restrict__ gamma,
                                      const float* __restrict__ beta,
                                      const float* __restrict__ fcW,    // [64][64]
                                      const float* __restrict__ fcb,
                                      int N)
{
    __shared__ float sW[D][D + 1];
    __shared__ float sF[D][D + 1];
    __shared__ float sb[D], sg[D], sbt[D], sfb[D];

    for (int i = threadIdx.x; i < D * D; i += blockDim.x) {
        sW[i >> 6][i & 63] = W[i];
        sF[i >> 6][i & 63] = fcW[i];
    }
    if (threadIdx.x < D) {
        sb[threadIdx.x]  = bias[threadIdx.x];
        sg[threadIdx.x]  = gamma[threadIdx.x];
        sbt[threadIdx.x] = beta[threadIdx.x];
        sfb[threadIdx.x] = fcb[threadIdx.x];
    }
    __syncthreads();

    const int warp = threadIdx.x >> 5;
    const int lane = threadIdx.x & 31;
    const int warps_per_grid = (blockDim.x >> 5) * gridDim.x;

    for (int r = blockIdx.x * (blockDim.x >> 5) + warp; r < N; r += warps_per_grid) {
        float hi0 = hin[(size_t)r * D + lane];
        float hi1 = hin[(size_t)r * D + lane + 32];
        float c = __ldg(cvec + r);

        float a0 = agg[(size_t)r * D + lane]      - c * hi0;
        float a1 = agg[(size_t)r * D + lane + 32] - c * hi1;

        float acc0 = 0.f, acc1 = 0.f;
#pragma unroll
        for (int k = 0; k < 32; k++) {
            float ak = __shfl_sync(0xffffffffu, a0, k);
            acc0 = fmaf(ak, sW[lane][k], acc0);
            acc1 = fmaf(ak, sW[lane + 32][k], acc1);
        }
#pragma unroll
        for (int k = 0; k < 32; k++) {
            float ak = __shfl_sync(0xffffffffu, a1, k);
            acc0 = fmaf(ak, sW[lane][k + 32], acc0);
            acc1 = fmaf(ak, sW[lane + 32][k + 32], acc1);
        }

        float h0 = fmaxf(acc0 + sb[lane], 0.f);
        float h1 = fmaxf(acc1 + sb[lane + 32], 0.f);

        float s  = h0 + h1;
        float sq = h0 * h0 + h1 * h1;
#pragma unroll
        for (int o = 16; o > 0; o >>= 1) {
            s  += __shfl_xor_sync(0xffffffffu, s,  o);
            sq += __shfl_xor_sync(0xffffffffu, sq, o);
        }
        float mu  = s * (1.f / D);
        float var = sq * (1.f / D) - mu * mu;
        float inv = rsqrtf(var + 1e-5f);

        float h3_0 = (h0 - mu) * inv * sg[lane]      + sbt[lane]      + hi0;
        float h3_1 = (h1 - mu) * inv * sg[lane + 32] + sbt[lane + 32] + hi1;

        // out = h3 @ fcW^T + fcb
        float o0 = 0.f, o1 = 0.f;
#pragma unroll
        for (int k = 0; k < 32; k++) {
            float hk = __shfl_sync(0xffffffffu, h3_0, k);
            o0 = fmaf(hk, sF[lane][k], o0);
            o1 = fmaf(hk, sF[lane + 32][k], o1);
        }
#pragma unroll
        for (int k = 0; k < 32; k++) {
            float hk = __shfl_sync(0xffffffffu, h3_1, k);
            o0 = fmaf(hk, sF[lane][k + 32], o0);
            o1 = fmaf(hk, sF[lane + 32][k + 32], o1);
        }

        out[(size_t)r * D + lane]      = o0 + sfb[lane];
        out[(size_t)r * D + lane + 32] = o1 + sfb[lane + 32];
    }
}

// ---------------------------------------------------------------------------
extern "C" void kernel_launch(void* const* d_in, const int* in_sizes, int n_in,
                              void* d_out, int out_size)
{
    const float* x      = (const float*)d_in[0];
    const void*  eidx   = d_in[1];                 // int64 OR int32 — probed on device
    const float* eattr  = (const float*)d_in[2];
    const float* lin_w  = (const float*)d_in[3];   // [3][64][64]
    const float* lin_b  = (const float*)d_in[4];   // [3][64]
    const float* emlp_w = (const float*)d_in[5];   // [3][1][8]
    const float* emlp_b = (const float*)d_in[6];   // [3][1]
    const float* gamma  = (const float*)d_in[7];   // [3][64]
    const float* beta   = (const float*)d_in[8];   // [3][64]
    const float* fc_w   = (const float*)d_in[9];   // [64][64]
    const float* fc_b   = (const float*)d_in[10];  // [64]
    float*       out    = (float*)d_out;

    const int E = in_sizes[1] / 2;
    const int N = in_sizes[0] / D;

    float *w_ptr, *c_ptr, *agg, *hA, *hB;
    int   *srcp, *dstp;
    cudaGetSymbolAddress((void**)&w_ptr, g_w);
    cudaGetSymbolAddress((void**)&c_ptr, g_c);
    cudaGetSymbolAddress((void**)&agg,   g_agg);
    cudaGetSymbolAddress((void**)&hA,    g_hA);
    cudaGetSymbolAddress((void**)&hB,    g_hB);
    cudaGetSymbolAddress((void**)&srcp,  g_src);
    cudaGetSymbolAddress((void**)&dstp,  g_dst);

    detect_kernel<<<1, 256>>>((const int*)eidx);
    zero_c_kernel<<<(NL * N + 255) / 256, 256>>>(NL * N);
    prep_kernel<<<(E + 255) / 256, 256>>>(eidx, eattr, emlp_w, emlp_b, E, N);

    const int n4 = N * D / 4;
    const long long scatter_threads = (long long)E * 16;
    const int scatter_blocks = (int)((scatter_threads + 255) / 256);

    const float* hin = x;
    float* houts[2] = { hA, hB };

    for (int l = 0; l < NL; l++) {
        zero_kernel<<<(n4 + 255) / 256, 256>>>((float4*)agg, n4);
        scatter_kernel<<<scatter_blocks, 256>>>(hin, agg, w_ptr + (size_t)l * E,
                                                srcp, dstp, E);
        if (l < NL - 1) {
            node_update_kernel<<<1480, 128>>>(agg, hin, houts[l],
                                              c_ptr + (size_t)l * N,
                                              lin_w + (size_t)l * D * D,
                                              lin_b + (size_t)l * D,
                                              gamma + (size_t)l * D,
                                              beta  + (size_t)l * D,
                                              N);
            hin = houts[l];
        } else {
            node_update_fc_kernel<<<1480, 128>>>(agg, hin, out,
                                                 c_ptr + (size_t)l * N,
                                                 lin_w + (size_t)l * D * D,
                                                 lin_b + (size_t)l * D,
                                                 gamma + (size_t)l * D,
                                                 beta  + (size_t)l * D,
                                                 fc_w, fc_b,
                                                 N);
        }
    }
}

// round 5
// speedup vs baseline: 1.2032x; 1.1898x over previous
#include <cuda_runtime.h>
#include <math.h>

#define N_NODES_MAX 100000
#define N_EDGES_MAX 3200000
#define D 64
#define NL 3

// ---- device scratch (no allocation allowed). 256B-aligned for float4 loads. ----
__device__ __align__(256) float g_wc[(size_t)NL * N_EDGES_MAX];  // CSR-ordered per-layer edge weights
__device__ __align__(256) int   g_srcc[N_EDGES_MAX];             // CSR-ordered source node ids
__device__ __align__(256) int   g_deg[N_NODES_MAX];              // in-degree histogram
__device__ __align__(256) int   g_offs[N_NODES_MAX + 1];         // CSR row offsets
__device__ __align__(256) int   g_cur[N_NODES_MAX];              // placement cursors
__device__ __align__(256) float g_hA[(size_t)N_NODES_MAX * D];
__device__ __align__(256) float g_hB[(size_t)N_NODES_MAX * D];
__device__ int g_is64;   // 1 if edge_index buffer is int64, 0 if int32

// ---------------------------------------------------------------------------
// Kernel 0: dtype probe for edge_index (int64 vs int32).
// ---------------------------------------------------------------------------
__global__ void detect_kernel(const int* __restrict__ w32)
{
    __shared__ int any;
    if (threadIdx.x == 0) any = 0;
    __syncthreads();
    int acc = 0;
    for (int i = threadIdx.x * 2 + 1; i < 4096; i += blockDim.x * 2)
        acc |= w32[i];
    if (acc) atomicOr(&any, 1);
    __syncthreads();
    if (threadIdx.x == 0) g_is64 = (any == 0) ? 1 : 0;
}

// ---------------------------------------------------------------------------
// Kernel 1: zero the degree histogram.
// ---------------------------------------------------------------------------
__global__ void zero_deg_kernel(int n)
{
    int i = blockIdx.x * blockDim.x + threadIdx.x;
    if (i < n) g_deg[i] = 0;
}

// ---------------------------------------------------------------------------
// Kernel 2: in-degree histogram over dst.
// ---------------------------------------------------------------------------
__global__ void hist_kernel(const void* __restrict__ eidx_raw, int E)
{
    int e = blockIdx.x * blockDim.x + threadIdx.x;
    if (e >= E) return;
    int d;
    if (g_is64) d = (int)((const long long*)eidx_raw)[(size_t)E + e];
    else        d = ((const int*)eidx_raw)[(size_t)E + e];
    atomicAdd(&g_deg[d], 1);
}

// ---------------------------------------------------------------------------
// Kernel 3: single-block exclusive scan -> g_offs, g_cur. blockDim = 1024.
// ---------------------------------------------------------------------------
__global__ void scan_kernel(int N)
{
    __shared__ int part[1024];
    const int tid = threadIdx.x;
    const int chunk = (N + 1023) >> 10;
    const int lo = tid * chunk;
    const int hi = min(lo + chunk, N);

    int sum = 0;
    for (int i = lo; i < hi; i++) sum += g_deg[i];
    part[tid] = sum;
    __syncthreads();

    // Hillis-Steele inclusive scan on 1024 partials
    for (int off = 1; off < 1024; off <<= 1) {
        int v  = part[tid];
        int vv = (tid >= off) ? part[tid - off] : 0;
        __syncthreads();
        part[tid] = v + vv;
        __syncthreads();
    }
    int run = (tid == 0) ? 0 : part[tid - 1];

    for (int i = lo; i < hi; i++) {
        int dg = g_deg[i];
        g_offs[i] = run;
        g_cur[i]  = run;
        run += dg;
    }
    if (hi == N && lo < N) g_offs[N] = run;
    if (N <= lo && tid == 0) g_offs[N] = 0;  // degenerate safety
}

// ---------------------------------------------------------------------------
// Kernel 4: edge placement into CSR slots + softplus weights for all 3 layers.
// ---------------------------------------------------------------------------
__global__ void place_kernel(const void* __restrict__ eidx_raw,
                             const float* __restrict__ eattr,
                             const float* __restrict__ emlp_w,   // [3][1][8]
                             const float* __restrict__ emlp_b,   // [3][1]
                             int E)
{
    int e = blockIdx.x * blockDim.x + threadIdx.x;
    if (e >= E) return;

    int s, d;
    if (g_is64) {
        const long long* p = (const long long*)eidx_raw;
        s = (int)p[e];
        d = (int)p[(size_t)E + e];
    } else {
        const int* p = (const int*)eidx_raw;
        s = p[e];
        d = p[(size_t)E + e];
    }

    int pos = atomicAdd(&g_cur[d], 1);
    g_srcc[pos] = s;

    const float4 a0 = *(const float4*)(eattr + (size_t)e * 8);
    const float4 a1 = *(const float4*)(eattr + (size_t)e * 8 + 4);

#pragma unroll
    for (int l = 0; l < NL; l++) {
        const float* wp = emlp_w + l * 8;
        float z = emlp_b[l];
        z = fmaf(a0.x, wp[0], z);
        z = fmaf(a0.y, wp[1], z);
        z = fmaf(a0.z, wp[2], z);
        z = fmaf(a0.w, wp[3], z);
        z = fmaf(a1.x, wp[4], z);
        z = fmaf(a1.y, wp[5], z);
        z = fmaf(a1.z, wp[6], z);
        z = fmaf(a1.w, wp[7], z);
        // numerically stable softplus = max(z,0) + log1p(exp(-|z|))
        float sp = fmaxf(z, 0.f) + log1pf(expf(-fabsf(z)));
        g_wc[(size_t)l * E + pos] = sp;
    }
}

// ---------------------------------------------------------------------------
// Fused per-layer kernel (no atomics, no agg buffer):
// warp per node r:
//   a = sum_{edges->r} w * h[src]  - (sum w) * h[r]
//   h' = LN(relu(a @ W^T + b)) * gamma + beta + h[r]
// Edge loop: 2 edges/iter, 16 float4-lanes per edge.
// ---------------------------------------------------------------------------
template <bool FUSE_FC>
__global__ void layer_kernel(const float* __restrict__ hin,
                             float* __restrict__ hout,
                             const float* __restrict__ wl,      // CSR weights this layer
                             const float* __restrict__ W,       // [64][64]
                             const float* __restrict__ bias,    // [64]
                             const float* __restrict__ gamma,   // [64]
                             const float* __restrict__ beta,    // [64]
                             const float* __restrict__ fcW,     // [64][64] (if FUSE_FC)
                             const float* __restrict__ fcb,     // [64]
                             int N)
{
    __shared__ float sW[D][D + 1];
    __shared__ float sF[FUSE_FC ? D : 1][FUSE_FC ? (D + 1) : 1];
    __shared__ float sb[D], sg[D], sbt[D], sfb[D];
    __shared__ float sA[8][D];   // 8 warps per block

    for (int i = threadIdx.x; i < D * D; i += blockDim.x) {
        sW[i >> 6][i & 63] = W[i];
        if (FUSE_FC) sF[i >> 6][i & 63] = fcW[i];
    }
    if (threadIdx.x < D) {
        sb[threadIdx.x]  = bias[threadIdx.x];
        sg[threadIdx.x]  = gamma[threadIdx.x];
        sbt[threadIdx.x] = beta[threadIdx.x];
        if (FUSE_FC) sfb[threadIdx.x] = fcb[threadIdx.x];
    }
    __syncthreads();

    const int warp = threadIdx.x >> 5;
    const int lane = threadIdx.x & 31;
    const int f4   = lane & 15;     // which float4 of the 64-dim row
    const int half = lane >> 4;     // edge parity
    const int warps_per_grid = (blockDim.x >> 5) * gridDim.x;

    for (int r = blockIdx.x * (blockDim.x >> 5) + warp; r < N; r += warps_per_grid) {
        const int start = __ldg(g_offs + r);
        const int end   = __ldg(g_offs + r + 1);

        float4 acc = make_float4(0.f, 0.f, 0.f, 0.f);
        float cw = 0.f;

        for (int i = start + half; i < end; i += 2) {
            int s    = __ldg(g_srcc + i);
            float we = __ldg(wl + i);
            const float4 v = __ldg((const float4*)(hin + (size_t)s * D) + f4);
            acc.x = fmaf(we, v.x, acc.x);
            acc.y = fmaf(we, v.y, acc.y);
            acc.z = fmaf(we, v.z, acc.z);
            acc.w = fmaf(we, v.w, acc.w);
            cw += we;
        }

        // combine the two edge-parity halves (lanes l and l^16 hold partial sums)
        acc.x += __shfl_xor_sync(0xffffffffu, acc.x, 16);
        acc.y += __shfl_xor_sync(0xffffffffu, acc.y, 16);
        acc.z += __shfl_xor_sync(0xffffffffu, acc.z, 16);
        acc.w += __shfl_xor_sync(0xffffffffu, acc.w, 16);

        // c = sum w. each edge's w was accumulated by 16 lanes -> exact /16.
#pragma unroll
        for (int o = 16; o > 0; o >>= 1)
            cw += __shfl_xor_sync(0xffffffffu, cw, o);
        cw *= (1.f / 16.f);

        if (lane < 16) {
            sA[warp][f4 * 4 + 0] = acc.x;
            sA[warp][f4 * 4 + 1] = acc.y;
            sA[warp][f4 * 4 + 2] = acc.z;
            sA[warp][f4 * 4 + 3] = acc.w;
        }
        __syncwarp();

        float hi0 = hin[(size_t)r * D + lane];
        float hi1 = hin[(size_t)r * D + lane + 32];

        float a0 = sA[warp][lane]      - cw * hi0;
        float a1 = sA[warp][lane + 32] - cw * hi1;
        __syncwarp();

        float acc0 = 0.f, acc1 = 0.f;
#pragma unroll
        for (int k = 0; k < 32; k++) {
            float ak = __shfl_sync(0xffffffffu, a0, k);
            acc0 = fmaf(ak, sW[lane][k], acc0);
            acc1 = fmaf(ak, sW[lane + 32][k], acc1);
        }
#pragma unroll
        for (int k = 0; k < 32; k++) {
            float ak = __shfl_sync(0xffffffffu, a1, k);
            acc0 = fmaf(ak, sW[lane][k + 32], acc0);
            acc1 = fmaf(ak, sW[lane + 32][k + 32], acc1);
        }

        float h0 = fmaxf(acc0 + sb[lane], 0.f);
        float h1 = fmaxf(acc1 + sb[lane + 32], 0.f);

        float s2  = h0 + h1;
        float sq = h0 * h0 + h1 * h1;
#pragma unroll
        for (int o = 16; o > 0; o >>= 1) {
            s2 += __shfl_xor_sync(0xffffffffu, s2, o);
            sq += __shfl_xor_sync(0xffffffffu, sq, o);
        }
        float mu  = s2 * (1.f / D);
        float var = sq * (1.f / D) - mu * mu;
        float inv = rsqrtf(var + 1e-5f);

        float o0 = (h0 - mu) * inv * sg[lane]      + sbt[lane]      + hi0;
        float o1 = (h1 - mu) * inv * sg[lane + 32] + sbt[lane + 32] + hi1;

        if (FUSE_FC) {
            float f0 = 0.f, f1 = 0.f;
#pragma unroll
            for (int k = 0; k < 32; k++) {
                float hk = __shfl_sync(0xffffffffu, o0, k);
                f0 = fmaf(hk, sF[lane][k], f0);
                f1 = fmaf(hk, sF[lane + 32][k], f1);
            }
#pragma unroll
            for (int k = 0; k < 32; k++) {
                float hk = __shfl_sync(0xffffffffu, o1, k);
                f0 = fmaf(hk, sF[lane][k + 32], f0);
                f1 = fmaf(hk, sF[lane + 32][k + 32], f1);
            }
            hout[(size_t)r * D + lane]      = f0 + sfb[lane];
            hout[(size_t)r * D + lane + 32] = f1 + sfb[lane + 32];
        } else {
            hout[(size_t)r * D + lane]      = o0;
            hout[(size_t)r * D + lane + 32] = o1;
        }
    }
}

// ---------------------------------------------------------------------------
extern "C" void kernel_launch(void* const* d_in, const int* in_sizes, int n_in,
                              void* d_out, int out_size)
{
    const float* x      = (const float*)d_in[0];
    const void*  eidx   = d_in[1];                 // int64 OR int32 — probed on device
    const float* eattr  = (const float*)d_in[2];
    const float* lin_w  = (const float*)d_in[3];   // [3][64][64]
    const float* lin_b  = (const float*)d_in[4];   // [3][64]
    const float* emlp_w = (const float*)d_in[5];   // [3][1][8]
    const float* emlp_b = (const float*)d_in[6];   // [3][1]
    const float* gamma  = (const float*)d_in[7];   // [3][64]
    const float* beta   = (const float*)d_in[8];   // [3][64]
    const float* fc_w   = (const float*)d_in[9];   // [64][64]
    const float* fc_b   = (const float*)d_in[10];  // [64]
    float*       out    = (float*)d_out;

    const int E = in_sizes[1] / 2;
    const int N = in_sizes[0] / D;

    float *wc_ptr, *hA, *hB;
    cudaGetSymbolAddress((void**)&wc_ptr, g_wc);
    cudaGetSymbolAddress((void**)&hA,     g_hA);
    cudaGetSymbolAddress((void**)&hB,     g_hB);

    // --- CSR build + edge weights ---
    detect_kernel<<<1, 256>>>((const int*)eidx);
    zero_deg_kernel<<<(N + 255) / 256, 256>>>(N);
    hist_kernel<<<(E + 255) / 256, 256>>>(eidx, E);
    scan_kernel<<<1, 1024>>>(N);
    place_kernel<<<(E + 255) / 256, 256>>>(eidx, eattr, emlp_w, emlp_b, E);

    // --- layers (fused gather + GEMM + LN + residual) ---
    const int blocks = 2048, threads = 256;

    layer_kernel<false><<<blocks, threads>>>(x,  hA, wc_ptr,
                                             lin_w, lin_b, gamma, beta,
                                             nullptr, nullptr, N);
    layer_kernel<false><<<blocks, threads>>>(hA, hB, wc_ptr + (size_t)E,
                                             lin_w + (size_t)D * D, lin_b + D,
                                             gamma + D, beta + D,
                                             nullptr, nullptr, N);
    layer_kernel<true><<<blocks, threads>>>(hB, out, wc_ptr + (size_t)2 * E,
                                            lin_w + (size_t)2 * D * D, lin_b + 2 * D,
                                            gamma + 2 * D, beta + 2 * D,
                                            fc_w, fc_b, N);
}

// round 6
// speedup vs baseline: 1.5483x; 1.2868x over previous
#include <cuda_runtime.h>
#include <math.h>

#define N_NODES_MAX 100000
#define N_EDGES_MAX 3200000
#define D 64
#define NL 3
#define SCAN_B 256
#define MAX_NB ((N_NODES_MAX + SCAN_B - 1) / SCAN_B + 1)

// ---- device scratch (no allocation allowed). 256B-aligned for float4 loads. ----
__device__ __align__(256) float g_wc[(size_t)NL * N_EDGES_MAX];  // CSR-ordered per-layer edge weights
__device__ __align__(256) int   g_srcc[N_EDGES_MAX];             // CSR-ordered source node ids
__device__ __align__(256) int   g_deg[N_NODES_MAX];              // in-degree histogram
__device__ __align__(256) int   g_offs[N_NODES_MAX + 1];         // CSR row offsets
__device__ __align__(256) int   g_cur[N_NODES_MAX];              // placement cursors
__device__ __align__(256) int   g_bsum[MAX_NB];                  // per-block partial sums
__device__ __align__(256) int   g_boff[MAX_NB];                  // per-block exclusive offsets
__device__ __align__(256) float g_hA[(size_t)N_NODES_MAX * D];
__device__ __align__(256) float g_hB[(size_t)N_NODES_MAX * D];
__device__ int g_is64;   // 1 if edge_index buffer is int64, 0 if int32

// ---------------------------------------------------------------------------
// Kernel 0: dtype probe for edge_index (int64 vs int32).
// ---------------------------------------------------------------------------
__global__ void detect_kernel(const int* __restrict__ w32)
{
    __shared__ int any;
    if (threadIdx.x == 0) any = 0;
    __syncthreads();
    int acc = 0;
    for (int i = threadIdx.x * 2 + 1; i < 4096; i += blockDim.x * 2)
        acc |= w32[i];
    if (acc) atomicOr(&any, 1);
    __syncthreads();
    if (threadIdx.x == 0) g_is64 = (any == 0) ? 1 : 0;
}

// ---------------------------------------------------------------------------
// Kernel 1: zero the degree histogram.
// ---------------------------------------------------------------------------
__global__ void zero_deg_kernel(int n)
{
    int i = blockIdx.x * blockDim.x + threadIdx.x;
    if (i < n) g_deg[i] = 0;
}

// ---------------------------------------------------------------------------
// Kernel 2: in-degree histogram over dst.
// ---------------------------------------------------------------------------
__global__ void hist_kernel(const void* __restrict__ eidx_raw, int E)
{
    int e = blockIdx.x * blockDim.x + threadIdx.x;
    if (e >= E) return;
    int d;
    if (g_is64) d = (int)((const long long*)eidx_raw)[(size_t)E + e];
    else        d = ((const int*)eidx_raw)[(size_t)E + e];
    atomicAdd(&g_deg[d], 1);
}

// ---------------------------------------------------------------------------
// Kernel 3a: per-block local exclusive scan of degrees; block totals -> g_bsum.
// ---------------------------------------------------------------------------
__global__ void scan_phase1(int N)
{
    __shared__ int sh[SCAN_B];
    const int tid = threadIdx.x;
    const int i = blockIdx.x * SCAN_B + tid;
    int v = (i < N) ? g_deg[i] : 0;
    sh[tid] = v;
    __syncthreads();
    for (int off = 1; off < SCAN_B; off <<= 1) {
        int a = sh[tid];
        int b = (tid >= off) ? sh[tid - off] : 0;
        __syncthreads();
        sh[tid] = a + b;
        __syncthreads();
    }
    if (i < N) g_offs[i] = sh[tid] - v;           // local exclusive
    if (tid == SCAN_B - 1) g_bsum[blockIdx.x] = sh[SCAN_B - 1];
}

// ---------------------------------------------------------------------------
// Kernel 3b: single-block scan of block sums -> exclusive block offsets.
// NB <= 1024 (N <= 262144).
// ---------------------------------------------------------------------------
__global__ void scan_phase2(int NB)
{
    __shared__ int sh[1024];
    const int tid = threadIdx.x;
    int v = (tid < NB) ? g_bsum[tid] : 0;
    sh[tid] = v;
    __syncthreads();
    for (int off = 1; off < 1024; off <<= 1) {
        int a = sh[tid];
        int b = (tid >= off) ? sh[tid - off] : 0;
        __syncthreads();
        sh[tid] = a + b;
        __syncthreads();
    }
    if (tid < NB) g_boff[tid] = sh[tid] - v;
}

// ---------------------------------------------------------------------------
// Kernel 3c: add block offsets; fill g_cur and g_offs[N].
// ---------------------------------------------------------------------------
__global__ void scan_phase3(int N)
{
    const int i = blockIdx.x * SCAN_B + threadIdx.x;
    if (i < N) {
        int o = g_offs[i] + g_boff[blockIdx.x];
        g_offs[i] = o;
        g_cur[i]  = o;
        if (i == N - 1) g_offs[N] = o + g_deg[i];
    }
}

// ---------------------------------------------------------------------------
// Kernel 4: edge placement into CSR slots + softplus weights for all 3 layers.
// ---------------------------------------------------------------------------
__global__ void place_kernel(const void* __restrict__ eidx_raw,
                             const float* __restrict__ eattr,
                             const float* __restrict__ emlp_w,   // [3][1][8]
                             const float* __restrict__ emlp_b,   // [3][1]
                             int E)
{
    int e = blockIdx.x * blockDim.x + threadIdx.x;
    if (e >= E) return;

    int s, d;
    if (g_is64) {
        const long long* p = (const long long*)eidx_raw;
        s = (int)p[e];
        d = (int)p[(size_t)E + e];
    } else {
        const int* p = (const int*)eidx_raw;
        s = p[e];
        d = p[(size_t)E + e];
    }

    int pos = atomicAdd(&g_cur[d], 1);
    g_srcc[pos] = s;

    const float4 a0 = *(const float4*)(eattr + (size_t)e * 8);
    const float4 a1 = *(const float4*)(eattr + (size_t)e * 8 + 4);

#pragma unroll
    for (int l = 0; l < NL; l++) {
        const float* wp = emlp_w + l * 8;
        float z = emlp_b[l];
        z = fmaf(a0.x, wp[0], z);
        z = fmaf(a0.y, wp[1], z);
        z = fmaf(a0.z, wp[2], z);
        z = fmaf(a0.w, wp[3], z);
        z = fmaf(a1.x, wp[4], z);
        z = fmaf(a1.y, wp[5], z);
        z = fmaf(a1.z, wp[6], z);
        z = fmaf(a1.w, wp[7], z);
        // numerically stable softplus = max(z,0) + log1p(exp(-|z|))
        float sp = fmaxf(z, 0.f) + log1pf(expf(-fabsf(z)));
        g_wc[(size_t)l * E + pos] = sp;
    }
}

// ---------------------------------------------------------------------------
// Fused per-layer kernel (no atomics, no agg buffer):
// warp per node r:
//   a = sum_{edges->r} w * h[src]  - (sum w) * h[r]
//   h' = LN(relu(a @ W^T + b)) * gamma + beta + h[r]
// Edge loop: 2 edges in flight per step (16 float4-lanes each), manually
// unrolled x2 for 2 outstanding gathers per lane.
// ---------------------------------------------------------------------------
template <bool FUSE_FC>
__global__ void layer_kernel(const float* __restrict__ hin,
                             float* __restrict__ hout,
                             const float* __restrict__ wl,      // CSR weights this layer
                             const float* __restrict__ W,       // [64][64]
                             const float* __restrict__ bias,    // [64]
                             const float* __restrict__ gamma,   // [64]
                             const float* __restrict__ beta,    // [64]
                             const float* __restrict__ fcW,     // [64][64] (if FUSE_FC)
                             const float* __restrict__ fcb,     // [64]
                             int N)
{
    __shared__ float sW[D][D + 1];
    __shared__ float sF[FUSE_FC ? D : 1][FUSE_FC ? (D + 1) : 1];
    __shared__ float sb[D], sg[D], sbt[D], sfb[D];
    __shared__ float sA[8][D];   // 8 warps per block

    for (int i = threadIdx.x; i < D * D; i += blockDim.x) {
        sW[i >> 6][i & 63] = W[i];
        if (FUSE_FC) sF[i >> 6][i & 63] = fcW[i];
    }
    if (threadIdx.x < D) {
        sb[threadIdx.x]  = bias[threadIdx.x];
        sg[threadIdx.x]  = gamma[threadIdx.x];
        sbt[threadIdx.x] = beta[threadIdx.x];
        if (FUSE_FC) sfb[threadIdx.x] = fcb[threadIdx.x];
    }
    __syncthreads();

    const int warp = threadIdx.x >> 5;
    const int lane = threadIdx.x & 31;
    const int f4   = lane & 15;     // which float4 of the 64-dim row
    const int half = lane >> 4;     // edge parity
    const int warps_per_grid = (blockDim.x >> 5) * gridDim.x;

    for (int r = blockIdx.x * (blockDim.x >> 5) + warp; r < N; r += warps_per_grid) {
        const int start = __ldg(g_offs + r);
        const int end   = __ldg(g_offs + r + 1);

        float4 acc  = make_float4(0.f, 0.f, 0.f, 0.f);
        float4 acc2 = make_float4(0.f, 0.f, 0.f, 0.f);
        float cw = 0.f, cw2 = 0.f;

        int i = start + half;
        // 2 edges per lane in flight (i and i+2)
        for (; i + 2 < end; i += 4) {
            int s1    = __ldg(g_srcc + i);
            int s2    = __ldg(g_srcc + i + 2);
            float w1  = __ldg(wl + i);
            float w2  = __ldg(wl + i + 2);
            const float4 v1 = __ldg((const float4*)(hin + (size_t)s1 * D) + f4);
            const float4 v2 = __ldg((const float4*)(hin + (size_t)s2 * D) + f4);
            acc.x  = fmaf(w1, v1.x, acc.x);
            acc.y  = fmaf(w1, v1.y, acc.y);
            acc.z  = fmaf(w1, v1.z, acc.z);
            acc.w  = fmaf(w1, v1.w, acc.w);
            cw += w1;
            acc2.x = fmaf(w2, v2.x, acc2.x);
            acc2.y = fmaf(w2, v2.y, acc2.y);
            acc2.z = fmaf(w2, v2.z, acc2.z);
            acc2.w = fmaf(w2, v2.w, acc2.w);
            cw2 += w2;
        }
        for (; i < end; i += 2) {
            int s    = __ldg(g_srcc + i);
            float we = __ldg(wl + i);
            const float4 v = __ldg((const float4*)(hin + (size_t)s * D) + f4);
            acc.x = fmaf(we, v.x, acc.x);
            acc.y = fmaf(we, v.y, acc.y);
            acc.z = fmaf(we, v.z, acc.z);
            acc.w = fmaf(we, v.w, acc.w);
            cw += we;
        }
        acc.x += acc2.x; acc.y += acc2.y; acc.z += acc2.z; acc.w += acc2.w;
        cw += cw2;

        // combine the two edge-parity halves (lanes l and l^16 hold partial sums)
        acc.x += __shfl_xor_sync(0xffffffffu, acc.x, 16);
        acc.y += __shfl_xor_sync(0xffffffffu, acc.y, 16);
        acc.z += __shfl_xor_sync(0xffffffffu, acc.z, 16);
        acc.w += __shfl_xor_sync(0xffffffffu, acc.w, 16);

        // c = sum w. each edge's w was accumulated by 16 lanes -> exact /16.
#pragma unroll
        for (int o = 16; o > 0; o >>= 1)
            cw += __shfl_xor_sync(0xffffffffu, cw, o);
        cw *= (1.f / 16.f);

        if (lane < 16) {
            sA[warp][f4 * 4 + 0] = acc.x;
            sA[warp][f4 * 4 + 1] = acc.y;
            sA[warp][f4 * 4 + 2] = acc.z;
            sA[warp][f4 * 4 + 3] = acc.w;
        }
        __syncwarp();

        float hi0 = hin[(size_t)r * D + lane];
        float hi1 = hin[(size_t)r * D + lane + 32];

        float a0 = sA[warp][lane]      - cw * hi0;
        float a1 = sA[warp][lane + 32] - cw * hi1;
        __syncwarp();

        float acc0 = 0.f, acc1 = 0.f;
#pragma unroll
        for (int k = 0; k < 32; k++) {
            float ak = __shfl_sync(0xffffffffu, a0, k);
            acc0 = fmaf(ak, sW[lane][k], acc0);
            acc1 = fmaf(ak, sW[lane + 32][k], acc1);
        }
#pragma unroll
        for (int k = 0; k < 32; k++) {
            float ak = __shfl_sync(0xffffffffu, a1, k);
            acc0 = fmaf(ak, sW[lane][k + 32], acc0);
            acc1 = fmaf(ak, sW[lane + 32][k + 32], acc1);
        }

        float h0 = fmaxf(acc0 + sb[lane], 0.f);
        float h1 = fmaxf(acc1 + sb[lane + 32], 0.f);

        float s2  = h0 + h1;
        float sq = h0 * h0 + h1 * h1;
#pragma unroll
        for (int o = 16; o > 0; o >>= 1) {
            s2 += __shfl_xor_sync(0xffffffffu, s2, o);
            sq += __shfl_xor_sync(0xffffffffu, sq, o);
        }
        float mu  = s2 * (1.f / D);
        float var = sq * (1.f / D) - mu * mu;
        float inv = rsqrtf(var + 1e-5f);

        float o0 = (h0 - mu) * inv * sg[lane]      + sbt[lane]      + hi0;
        float o1 = (h1 - mu) * inv * sg[lane + 32] + sbt[lane + 32] + hi1;

        if (FUSE_FC) {
            float f0 = 0.f, f1 = 0.f;
#pragma unroll
            for (int k = 0; k < 32; k++) {
                float hk = __shfl_sync(0xffffffffu, o0, k);
                f0 = fmaf(hk, sF[lane][k], f0);
                f1 = fmaf(hk, sF[lane + 32][k], f1);
            }
#pragma unroll
            for (int k = 0; k < 32; k++) {
                float hk = __shfl_sync(0xffffffffu, o1, k);
                f0 = fmaf(hk, sF[lane][k + 32], f0);
                f1 = fmaf(hk, sF[lane + 32][k + 32], f1);
            }
            hout[(size_t)r * D + lane]      = f0 + sfb[lane];
            hout[(size_t)r * D + lane + 32] = f1 + sfb[lane + 32];
        } else {
            hout[(size_t)r * D + lane]      = o0;
            hout[(size_t)r * D + lane + 32] = o1;
        }
    }
}

// ---------------------------------------------------------------------------
extern "C" void kernel_launch(void* const* d_in, const int* in_sizes, int n_in,
                              void* d_out, int out_size)
{
    const float* x      = (const float*)d_in[0];
    const void*  eidx   = d_in[1];                 // int64 OR int32 — probed on device
    const float* eattr  = (const float*)d_in[2];
    const float* lin_w  = (const float*)d_in[3];   // [3][64][64]
    const float* lin_b  = (const float*)d_in[4];   // [3][64]
    const float* emlp_w = (const float*)d_in[5];   // [3][1][8]
    const float* emlp_b = (const float*)d_in[6];   // [3][1]
    const float* gamma  = (const float*)d_in[7];   // [3][64]
    const float* beta   = (const float*)d_in[8];   // [3][64]
    const float* fc_w   = (const float*)d_in[9];   // [64][64]
    const float* fc_b   = (const float*)d_in[10];  // [64]
    float*       out    = (float*)d_out;

    const int E = in_sizes[1] / 2;
    const int N = in_sizes[0] / D;

    float *wc_ptr, *hA, *hB;
    cudaGetSymbolAddress((void**)&wc_ptr, g_wc);
    cudaGetSymbolAddress((void**)&hA,     g_hA);
    cudaGetSymbolAddress((void**)&hB,     g_hB);

    // --- CSR build + edge weights ---
    const int NB = (N + SCAN_B - 1) / SCAN_B;
    detect_kernel<<<1, 256>>>((const int*)eidx);
    zero_deg_kernel<<<(N + 255) / 256, 256>>>(N);
    hist_kernel<<<(E + 255) / 256, 256>>>(eidx, E);
    scan_phase1<<<NB, SCAN_B>>>(N);
    scan_phase2<<<1, 1024>>>(NB);
    scan_phase3<<<NB, SCAN_B>>>(N);
    place_kernel<<<(E + 255) / 256, 256>>>(eidx, eattr, emlp_w, emlp_b, E);

    // --- layers (fused gather + GEMM + LN + residual) ---
    const int blocks = 2048, threads = 256;

    layer_kernel<false><<<blocks, threads>>>(x,  hA, wc_ptr,
                                             lin_w, lin_b, gamma, beta,
                                             nullptr, nullptr, N);
    layer_kernel<false><<<blocks, threads>>>(hA, hB, wc_ptr + (size_t)E,
                                             lin_w + (size_t)D * D, lin_b + D,
                                             gamma + D, beta + D,
                                             nullptr, nullptr, N);
    layer_kernel<true><<<blocks, threads>>>(hB, out, wc_ptr + (size_t)2 * E,
                                            lin_w + (size_t)2 * D * D, lin_b + 2 * D,
                                            gamma + 2 * D, beta + 2 * D,
                                            fc_w, fc_b, N);
}

// round 7
// speedup vs baseline: 1.6502x; 1.0658x over previous
#include <cuda_runtime.h>
#include <math.h>

#define N_NODES_MAX 100000
#define N_EDGES_MAX 3200000
#define D 64
#define NL 3
#define SCAN_B 256
#define MAX_NB ((N_NODES_MAX + SCAN_B - 1) / SCAN_B + 1)

// ---- device scratch (no allocation allowed). 256B-aligned for float4 loads. ----
// Edge record: .x = src id (bit-cast int), .y/.z/.w = softplus weight for layer 0/1/2
__device__ __align__(256) float4 g_edges[N_EDGES_MAX];
__device__ __align__(256) int   g_deg[N_NODES_MAX];              // in-degree histogram
__device__ __align__(256) int   g_offs[N_NODES_MAX + 1];         // CSR row offsets
__device__ __align__(256) int   g_cur[N_NODES_MAX];              // placement cursors
__device__ __align__(256) int   g_bsum[MAX_NB];                  // per-block partial sums
__device__ __align__(256) int   g_boff[MAX_NB];                  // per-block exclusive offsets
__device__ __align__(256) float g_hA[(size_t)N_NODES_MAX * D];
__device__ __align__(256) float g_hB[(size_t)N_NODES_MAX * D];
__device__ int g_is64;   // 1 if edge_index buffer is int64, 0 if int32

// ---------------------------------------------------------------------------
// Kernel 0: dtype probe for edge_index (int64 vs int32).
// ---------------------------------------------------------------------------
__global__ void detect_kernel(const int* __restrict__ w32)
{
    __shared__ int any;
    if (threadIdx.x == 0) any = 0;
    __syncthreads();
    int acc = 0;
    for (int i = threadIdx.x * 2 + 1; i < 4096; i += blockDim.x * 2)
        acc |= w32[i];
    if (acc) atomicOr(&any, 1);
    __syncthreads();
    if (threadIdx.x == 0) g_is64 = (any == 0) ? 1 : 0;
}

// ---------------------------------------------------------------------------
// Kernel 1: zero the degree histogram.
// ---------------------------------------------------------------------------
__global__ void zero_deg_kernel(int n)
{
    int i = blockIdx.x * blockDim.x + threadIdx.x;
    if (i < n) g_deg[i] = 0;
}

// ---------------------------------------------------------------------------
// Kernel 2: in-degree histogram over dst.
// ---------------------------------------------------------------------------
__global__ void hist_kernel(const void* __restrict__ eidx_raw, int E)
{
    int e = blockIdx.x * blockDim.x + threadIdx.x;
    if (e >= E) return;
    int d;
    if (g_is64) d = (int)((const long long*)eidx_raw)[(size_t)E + e];
    else        d = ((const int*)eidx_raw)[(size_t)E + e];
    atomicAdd(&g_deg[d], 1);
}

// ---------------------------------------------------------------------------
// Kernel 3a: per-block local exclusive scan of degrees; block totals -> g_bsum.
// ---------------------------------------------------------------------------
__global__ void scan_phase1(int N)
{
    __shared__ int sh[SCAN_B];
    const int tid = threadIdx.x;
    const int i = blockIdx.x * SCAN_B + tid;
    int v = (i < N) ? g_deg[i] : 0;
    sh[tid] = v;
    __syncthreads();
    for (int off = 1; off < SCAN_B; off <<= 1) {
        int a = sh[tid];
        int b = (tid >= off) ? sh[tid - off] : 0;
        __syncthreads();
        sh[tid] = a + b;
        __syncthreads();
    }
    if (i < N) g_offs[i] = sh[tid] - v;           // local exclusive
    if (tid == SCAN_B - 1) g_bsum[blockIdx.x] = sh[SCAN_B - 1];
}

// ---------------------------------------------------------------------------
// Kernel 3b: single-block scan of block sums -> exclusive block offsets.
// NB <= 1024 (N <= 262144).
// ---------------------------------------------------------------------------
__global__ void scan_phase2(int NB)
{
    __shared__ int sh[1024];
    const int tid = threadIdx.x;
    int v = (tid < NB) ? g_bsum[tid] : 0;
    sh[tid] = v;
    __syncthreads();
    for (int off = 1; off < 1024; off <<= 1) {
        int a = sh[tid];
        int b = (tid >= off) ? sh[tid - off] : 0;
        __syncthreads();
        sh[tid] = a + b;
        __syncthreads();
    }
    if (tid < NB) g_boff[tid] = sh[tid] - v;
}

// ---------------------------------------------------------------------------
// Kernel 3c: add block offsets; fill g_cur and g_offs[N].
// ---------------------------------------------------------------------------
__global__ void scan_phase3(int N)
{
    const int i = blockIdx.x * SCAN_B + threadIdx.x;
    if (i < N) {
        int o = g_offs[i] + g_boff[blockIdx.x];
        g_offs[i] = o;
        g_cur[i]  = o;
        if (i == N - 1) g_offs[N] = o + g_deg[i];
    }
}

// ---------------------------------------------------------------------------
// Kernel 4: edge placement into CSR slots. One 16B record per edge:
// {src, w_layer0, w_layer1, w_layer2}.
// ---------------------------------------------------------------------------
__global__ void place_kernel(const void* __restrict__ eidx_raw,
                             const float* __restrict__ eattr,
                             const float* __restrict__ emlp_w,   // [3][1][8]
                             const float* __restrict__ emlp_b,   // [3][1]
                             int E)
{
    int e = blockIdx.x * blockDim.x + threadIdx.x;
    if (e >= E) return;

    int s, d;
    if (g_is64) {
        const long long* p = (const long long*)eidx_raw;
        s = (int)p[e];
        d = (int)p[(size_t)E + e];
    } else {
        const int* p = (const int*)eidx_raw;
        s = p[e];
        d = p[(size_t)E + e];
    }

    const float4 a0 = *(const float4*)(eattr + (size_t)e * 8);
    const float4 a1 = *(const float4*)(eattr + (size_t)e * 8 + 4);

    float sp[NL];
#pragma unroll
    for (int l = 0; l < NL; l++) {
        const float* wp = emlp_w + l * 8;
        float z = emlp_b[l];
        z = fmaf(a0.x, wp[0], z);
        z = fmaf(a0.y, wp[1], z);
        z = fmaf(a0.z, wp[2], z);
        z = fmaf(a0.w, wp[3], z);
        z = fmaf(a1.x, wp[4], z);
        z = fmaf(a1.y, wp[5], z);
        z = fmaf(a1.z, wp[6], z);
        z = fmaf(a1.w, wp[7], z);
        // numerically stable softplus = max(z,0) + log1p(exp(-|z|))
        sp[l] = fmaxf(z, 0.f) + log1pf(expf(-fabsf(z)));
    }

    int pos = atomicAdd(&g_cur[d], 1);
    g_edges[pos] = make_float4(__int_as_float(s), sp[0], sp[1], sp[2]);
}

// ---------------------------------------------------------------------------
// Fused per-layer kernel (no atomics, no agg buffer):
// warp per node r:
//   a = sum_{edges->r} w * h[src]  - (sum w) * h[r]
//   h' = LN(relu(a @ W^T + b)) * gamma + beta + h[r]
// Edge loop: lanes split into 2 halves (one edge each); each half keeps up to
// 4 edge records + 4 feature gathers in flight (MLP=4).
// ---------------------------------------------------------------------------
template <int L, bool FUSE_FC>
__global__ void layer_kernel(const float* __restrict__ hin,
                             float* __restrict__ hout,
                             const float* __restrict__ W,       // [64][64]
                             const float* __restrict__ bias,    // [64]
                             const float* __restrict__ gamma,   // [64]
                             const float* __restrict__ beta,    // [64]
                             const float* __restrict__ fcW,     // [64][64] (if FUSE_FC)
                             const float* __restrict__ fcb,     // [64]
                             int N)
{
    __shared__ float sW[D][D + 1];
    __shared__ float sF[FUSE_FC ? D : 1][FUSE_FC ? (D + 1) : 1];
    __shared__ float sb[D], sg[D], sbt[D], sfb[D];
    __shared__ float sA[8][D];   // 8 warps per block

    for (int i = threadIdx.x; i < D * D; i += blockDim.x) {
        sW[i >> 6][i & 63] = W[i];
        if (FUSE_FC) sF[i >> 6][i & 63] = fcW[i];
    }
    if (threadIdx.x < D) {
        sb[threadIdx.x]  = bias[threadIdx.x];
        sg[threadIdx.x]  = gamma[threadIdx.x];
        sbt[threadIdx.x] = beta[threadIdx.x];
        if (FUSE_FC) sfb[threadIdx.x] = fcb[threadIdx.x];
    }
    __syncthreads();

    const int warp = threadIdx.x >> 5;
    const int lane = threadIdx.x & 31;
    const int f4   = lane & 15;     // which float4 of the 64-dim row
    const int half = lane >> 4;     // edge parity
    const int warps_per_grid = (blockDim.x >> 5) * gridDim.x;

    for (int r = blockIdx.x * (blockDim.x >> 5) + warp; r < N; r += warps_per_grid) {
        const int start = __ldg(g_offs + r);
        const int end   = __ldg(g_offs + r + 1);

        float4 acc  = make_float4(0.f, 0.f, 0.f, 0.f);
        float4 acc2 = make_float4(0.f, 0.f, 0.f, 0.f);
        float cw = 0.f, cw2 = 0.f;

        int i = start + half;
        // 4 edges in flight per lane-half (stride 2 between the halves' edges)
        for (; i + 6 < end; i += 8) {
            float4 r0 = __ldg(g_edges + i);
            float4 r1 = __ldg(g_edges + i + 2);
            float4 r2 = __ldg(g_edges + i + 4);
            float4 r3 = __ldg(g_edges + i + 6);
            float w0 = (L == 0) ? r0.y : (L == 1) ? r0.z : r0.w;
            float w1 = (L == 0) ? r1.y : (L == 1) ? r1.z : r1.w;
            float w2 = (L == 0) ? r2.y : (L == 1) ? r2.z : r2.w;
            float w3 = (L == 0) ? r3.y : (L == 1) ? r3.z : r3.w;
            const float4 v0 = __ldg((const float4*)(hin + (size_t)__float_as_int(r0.x) * D) + f4);
            const float4 v1 = __ldg((const float4*)(hin + (size_t)__float_as_int(r1.x) * D) + f4);
            const float4 v2 = __ldg((const float4*)(hin + (size_t)__float_as_int(r2.x) * D) + f4);
            const float4 v3 = __ldg((const float4*)(hin + (size_t)__float_as_int(r3.x) * D) + f4);
            acc.x  = fmaf(w0, v0.x, acc.x);  acc.y  = fmaf(w0, v0.y, acc.y);
            acc.z  = fmaf(w0, v0.z, acc.z);  acc.w  = fmaf(w0, v0.w, acc.w);
            cw += w0;
            acc2.x = fmaf(w1, v1.x, acc2.x); acc2.y = fmaf(w1, v1.y, acc2.y);
            acc2.z = fmaf(w1, v1.z, acc2.z); acc2.w = fmaf(w1, v1.w, acc2.w);
            cw2 += w1;
            acc.x  = fmaf(w2, v2.x, acc.x);  acc.y  = fmaf(w2, v2.y, acc.y);
            acc.z  = fmaf(w2, v2.z, acc.z);  acc.w  = fmaf(w2, v2.w, acc.w);
            cw += w2;
            acc2.x = fmaf(w3, v3.x, acc2.x); acc2.y = fmaf(w3, v3.y, acc2.y);
            acc2.z = fmaf(w3, v3.z, acc2.z); acc2.w = fmaf(w3, v3.w, acc2.w);
            cw2 += w3;
        }
        for (; i < end; i += 2) {
            float4 re = __ldg(g_edges + i);
            float we = (L == 0) ? re.y : (L == 1) ? re.z : re.w;
            const float4 v = __ldg((const float4*)(hin + (size_t)__float_as_int(re.x) * D) + f4);
            acc.x = fmaf(we, v.x, acc.x);
            acc.y = fmaf(we, v.y, acc.y);
            acc.z = fmaf(we, v.z, acc.z);
            acc.w = fmaf(we, v.w, acc.w);
            cw += we;
        }
        acc.x += acc2.x; acc.y += acc2.y; acc.z += acc2.z; acc.w += acc2.w;
        cw += cw2;

        // combine the two edge-parity halves (lanes l and l^16 hold partial sums)
        acc.x += __shfl_xor_sync(0xffffffffu, acc.x, 16);
        acc.y += __shfl_xor_sync(0xffffffffu, acc.y, 16);
        acc.z += __shfl_xor_sync(0xffffffffu, acc.z, 16);
        acc.w += __shfl_xor_sync(0xffffffffu, acc.w, 16);

        // c = sum w. each edge's w was accumulated by 16 lanes -> exact /16.
#pragma unroll
        for (int o = 16; o > 0; o >>= 1)
            cw += __shfl_xor_sync(0xffffffffu, cw, o);
        cw *= (1.f / 16.f);

        if (lane < 16) {
            sA[warp][f4 * 4 + 0] = acc.x;
            sA[warp][f4 * 4 + 1] = acc.y;
            sA[warp][f4 * 4 + 2] = acc.z;
            sA[warp][f4 * 4 + 3] = acc.w;
        }
        __syncwarp();

        float hi0 = hin[(size_t)r * D + lane];
        float hi1 = hin[(size_t)r * D + lane + 32];

        float a0 = sA[warp][lane]      - cw * hi0;
        float a1 = sA[warp][lane + 32] - cw * hi1;
        __syncwarp();

        float acc0 = 0.f, acc1 = 0.f;
#pragma unroll
        for (int k = 0; k < 32; k++) {
            float ak = __shfl_sync(0xffffffffu, a0, k);
            acc0 = fmaf(ak, sW[lane][k], acc0);
            acc1 = fmaf(ak, sW[lane + 32][k], acc1);
        }
#pragma unroll
        for (int k = 0; k < 32; k++) {
            float ak = __shfl_sync(0xffffffffu, a1, k);
            acc0 = fmaf(ak, sW[lane][k + 32], acc0);
            acc1 = fmaf(ak, sW[lane + 32][k + 32], acc1);
        }

        float h0 = fmaxf(acc0 + sb[lane], 0.f);
        float h1 = fmaxf(acc1 + sb[lane + 32], 0.f);

        float s2 = h0 + h1;
        float sq = h0 * h0 + h1 * h1;
#pragma unroll
        for (int o = 16; o > 0; o >>= 1) {
            s2 += __shfl_xor_sync(0xffffffffu, s2, o);
            sq += __shfl_xor_sync(0xffffffffu, sq, o);
        }
        float mu  = s2 * (1.f / D);
        float var = sq * (1.f / D) - mu * mu;
        float inv = rsqrtf(var + 1e-5f);

        float o0 = (h0 - mu) * inv * sg[lane]      + sbt[lane]      + hi0;
        float o1 = (h1 - mu) * inv * sg[lane + 32] + sbt[lane + 32] + hi1;

        if (FUSE_FC) {
            float f0 = 0.f, f1 = 0.f;
#pragma unroll
            for (int k = 0; k < 32; k++) {
                float hk = __shfl_sync(0xffffffffu, o0, k);
                f0 = fmaf(hk, sF[lane][k], f0);
                f1 = fmaf(hk, sF[lane + 32][k], f1);
            }
#pragma unroll
            for (int k = 0; k < 32; k++) {
                float hk = __shfl_sync(0xffffffffu, o1, k);
                f0 = fmaf(hk, sF[lane][k + 32], f0);
                f1 = fmaf(hk, sF[lane + 32][k + 32], f1);
            }
            hout[(size_t)r * D + lane]      = f0 + sfb[lane];
            hout[(size_t)r * D + lane + 32] = f1 + sfb[lane + 32];
        } else {
            hout[(size_t)r * D + lane]      = o0;
            hout[(size_t)r * D + lane + 32] = o1;
        }
    }
}

// ---------------------------------------------------------------------------
extern "C" void kernel_launch(void* const* d_in, const int* in_sizes, int n_in,
                              void* d_out, int out_size)
{
    const float* x      = (const float*)d_in[0];
    const void*  eidx   = d_in[1];                 // int64 OR int32 — probed on device
    const float* eattr  = (const float*)d_in[2];
    const float* lin_w  = (const float*)d_in[3];   // [3][64][64]
    const float* lin_b  = (const float*)d_in[4];   // [3][64]
    const float* emlp_w = (const float*)d_in[5];   // [3][1][8]
    const float* emlp_b = (const float*)d_in[6];   // [3][1]
    const float* gamma  = (const float*)d_in[7];   // [3][64]
    const float* beta   = (const float*)d_in[8];   // [3][64]
    const float* fc_w   = (const float*)d_in[9];   // [64][64]
    const float* fc_b   = (const float*)d_in[10];  // [64]
    float*       out    = (float*)d_out;

    const int E = in_sizes[1] / 2;
    const int N = in_sizes[0] / D;

    float *hA, *hB;
    cudaGetSymbolAddress((void**)&hA, g_hA);
    cudaGetSymbolAddress((void**)&hB, g_hB);

    // --- CSR build + edge weights ---
    const int NB = (N + SCAN_B - 1) / SCAN_B;
    detect_kernel<<<1, 256>>>((const int*)eidx);
    zero_deg_kernel<<<(N + 255) / 256, 256>>>(N);
    hist_kernel<<<(E + 255) / 256, 256>>>(eidx, E);
    scan_phase1<<<NB, SCAN_B>>>(N);
    scan_phase2<<<1, 1024>>>(NB);
    scan_phase3<<<NB, SCAN_B>>>(N);
    place_kernel<<<(E + 255) / 256, 256>>>(eidx, eattr, emlp_w, emlp_b, E);

    // --- layers (fused gather + GEMM + LN + residual) ---
    const int blocks = 2048, threads = 256;

    layer_kernel<0, false><<<blocks, threads>>>(x,  hA,
                                                lin_w, lin_b, gamma, beta,
                                                nullptr, nullptr, N);
    layer_kernel<1, false><<<blocks, threads>>>(hA, hB,
                                                lin_w + (size_t)D * D, lin_b + D,
                                                gamma + D, beta + D,
                                                nullptr, nullptr, N);
    layer_kernel<2, true><<<blocks, threads>>>(hB, out,
                                               lin_w + (size_t)2 * D * D, lin_b + 2 * D,
                                               gamma + 2 * D, beta + 2 * D,
                                               fc_w, fc_b, N);
}

// round 8
// speedup vs baseline: 1.7272x; 1.0467x over previous
#include <cuda_runtime.h>
#include <cuda_bf16.h>
#include <math.h>

#define N_NODES_MAX 100000
#define N_EDGES_MAX 3200000
#define D 64
#define NL 3
#define SCAN_B 256
#define MAX_NB ((N_NODES_MAX + SCAN_B - 1) / SCAN_B + 1)

// ---- device scratch (no allocation allowed). 256B-aligned for vector loads. ----
// Edge record: .x = src id (bit-cast int), .y/.z/.w = softplus weight for layer 0/1/2
__device__ __align__(256) float4 g_edges[N_EDGES_MAX];
__device__ __align__(256) int   g_deg[N_NODES_MAX];
__device__ __align__(256) int   g_offs[N_NODES_MAX + 1];
__device__ __align__(256) int   g_cur[N_NODES_MAX];
__device__ __align__(256) int   g_bsum[MAX_NB];
__device__ __align__(256) int   g_boff[MAX_NB];
__device__ __align__(256) float g_hA[(size_t)N_NODES_MAX * D];
__device__ __align__(256) float g_hB[(size_t)N_NODES_MAX * D];
__device__ __align__(256) __nv_bfloat16 g_xb [(size_t)N_NODES_MAX * D];  // bf16 shadow of layer inputs
__device__ __align__(256) __nv_bfloat16 g_hbA[(size_t)N_NODES_MAX * D];
__device__ __align__(256) __nv_bfloat16 g_hbB[(size_t)N_NODES_MAX * D];
__device__ int g_is64;

// ---------------------------------------------------------------------------
__global__ void detect_kernel(const int* __restrict__ w32)
{
    __shared__ int any;
    if (threadIdx.x == 0) any = 0;
    __syncthreads();
    int acc = 0;
    for (int i = threadIdx.x * 2 + 1; i < 4096; i += blockDim.x * 2)
        acc |= w32[i];
    if (acc) atomicOr(&any, 1);
    __syncthreads();
    if (threadIdx.x == 0) g_is64 = (any == 0) ? 1 : 0;
}

__global__ void zero_deg_kernel(int n)
{
    int i = blockIdx.x * blockDim.x + threadIdx.x;
    if (i < n) g_deg[i] = 0;
}

__global__ void hist_kernel(const void* __restrict__ eidx_raw, int E)
{
    int e = blockIdx.x * blockDim.x + threadIdx.x;
    if (e >= E) return;
    int d;
    if (g_is64) d = (int)((const long long*)eidx_raw)[(size_t)E + e];
    else        d = ((const int*)eidx_raw)[(size_t)E + e];
    atomicAdd(&g_deg[d], 1);
}

__global__ void scan_phase1(int N)
{
    __shared__ int sh[SCAN_B];
    const int tid = threadIdx.x;
    const int i = blockIdx.x * SCAN_B + tid;
    int v = (i < N) ? g_deg[i] : 0;
    sh[tid] = v;
    __syncthreads();
    for (int off = 1; off < SCAN_B; off <<= 1) {
        int a = sh[tid];
        int b = (tid >= off) ? sh[tid - off] : 0;
        __syncthreads();
        sh[tid] = a + b;
        __syncthreads();
    }
    if (i < N) g_offs[i] = sh[tid] - v;
    if (tid == SCAN_B - 1) g_bsum[blockIdx.x] = sh[SCAN_B - 1];
}

__global__ void scan_phase2(int NB)
{
    __shared__ int sh[1024];
    const int tid = threadIdx.x;
    int v = (tid < NB) ? g_bsum[tid] : 0;
    sh[tid] = v;
    __syncthreads();
    for (int off = 1; off < 1024; off <<= 1) {
        int a = sh[tid];
        int b = (tid >= off) ? sh[tid - off] : 0;
        __syncthreads();
        sh[tid] = a + b;
        __syncthreads();
    }
    if (tid < NB) g_boff[tid] = sh[tid] - v;
}

__global__ void scan_phase3(int N)
{
    const int i = blockIdx.x * SCAN_B + threadIdx.x;
    if (i < N) {
        int o = g_offs[i] + g_boff[blockIdx.x];
        g_offs[i] = o;
        g_cur[i]  = o;
        if (i == N - 1) g_offs[N] = o + g_deg[i];
    }
}

__global__ void place_kernel(const void* __restrict__ eidx_raw,
                             const float* __restrict__ eattr,
                             const float* __restrict__ emlp_w,
                             const float* __restrict__ emlp_b,
                             int E)
{
    int e = blockIdx.x * blockDim.x + threadIdx.x;
    if (e >= E) return;

    int s, d;
    if (g_is64) {
        const long long* p = (const long long*)eidx_raw;
        s = (int)p[e];
        d = (int)p[(size_t)E + e];
    } else {
        const int* p = (const int*)eidx_raw;
        s = p[e];
        d = p[(size_t)E + e];
    }

    const float4 a0 = *(const float4*)(eattr + (size_t)e * 8);
    const float4 a1 = *(const float4*)(eattr + (size_t)e * 8 + 4);

    float sp[NL];
#pragma unroll
    for (int l = 0; l < NL; l++) {
        const float* wp = emlp_w + l * 8;
        float z = emlp_b[l];
        z = fmaf(a0.x, wp[0], z);
        z = fmaf(a0.y, wp[1], z);
        z = fmaf(a0.z, wp[2], z);
        z = fmaf(a0.w, wp[3], z);
        z = fmaf(a1.x, wp[4], z);
        z = fmaf(a1.y, wp[5], z);
        z = fmaf(a1.z, wp[6], z);
        z = fmaf(a1.w, wp[7], z);
        sp[l] = fmaxf(z, 0.f) + log1pf(expf(-fabsf(z)));
    }

    int pos = atomicAdd(&g_cur[d], 1);
    g_edges[pos] = make_float4(__int_as_float(s), sp[0], sp[1], sp[2]);
}

// ---------------------------------------------------------------------------
// Convert x (fp32) -> bf16 shadow. n multiple of 4.
// ---------------------------------------------------------------------------
__global__ void f2bf_kernel(const float* __restrict__ in,
                            __nv_bfloat16* __restrict__ out, int n)
{
    int idx = (blockIdx.x * blockDim.x + threadIdx.x) * 4;
    if (idx < n) {
        float4 v = *(const float4*)(in + idx);
        *(__nv_bfloat162*)(out + idx)     = __floats2bfloat162_rn(v.x, v.y);
        *(__nv_bfloat162*)(out + idx + 2) = __floats2bfloat162_rn(v.z, v.w);
    }
}

// ---------------------------------------------------------------------------
// bf16 chunk (8 values) -> fma into 8 fp32 accumulators
// ---------------------------------------------------------------------------
__device__ __forceinline__ void cvt_fma8(float* acc, uint4 u, float w)
{
    float2 p;
    p = __bfloat1622float2(*reinterpret_cast<__nv_bfloat162*>(&u.x));
    acc[0] = fmaf(w, p.x, acc[0]); acc[1] = fmaf(w, p.y, acc[1]);
    p = __bfloat1622float2(*reinterpret_cast<__nv_bfloat162*>(&u.y));
    acc[2] = fmaf(w, p.x, acc[2]); acc[3] = fmaf(w, p.y, acc[3]);
    p = __bfloat1622float2(*reinterpret_cast<__nv_bfloat162*>(&u.z));
    acc[4] = fmaf(w, p.x, acc[4]); acc[5] = fmaf(w, p.y, acc[5]);
    p = __bfloat1622float2(*reinterpret_cast<__nv_bfloat162*>(&u.w));
    acc[6] = fmaf(w, p.x, acc[6]); acc[7] = fmaf(w, p.y, acc[7]);
}

// ---------------------------------------------------------------------------
// Fused per-layer kernel. Warp per node r:
//   a = sum_{edges->r} w * hb16[src]  - (sum w) * h[r]     (h[r] fp32)
//   h' = LN(relu(a @ W^T + b)) * gamma + beta + h[r]
// Gather: 4 edges per warp pass (8 lanes x 16B = 128B bf16 row each), x2 unroll.
// ---------------------------------------------------------------------------
template <int L, bool FUSE_FC>
__global__ void layer_kernel(const float* __restrict__ hin,
                             const __nv_bfloat16* __restrict__ hin_b,
                             float* __restrict__ hout,
                             __nv_bfloat16* __restrict__ hout_b,   // may be null
                             const float* __restrict__ W,
                             const float* __restrict__ bias,
                             const float* __restrict__ gamma,
                             const float* __restrict__ beta,
                             const float* __restrict__ fcW,
                             const float* __restrict__ fcb,
                             int N)
{
    __shared__ float sW[D][D + 1];
    __shared__ float sF[FUSE_FC ? D : 1][FUSE_FC ? (D + 1) : 1];
    __shared__ float sb[D], sg[D], sbt[D], sfb[D];
    __shared__ float sA[8][D];   // 8 warps per block

    for (int i = threadIdx.x; i < D * D; i += blockDim.x) {
        sW[i >> 6][i & 63] = W[i];
        if (FUSE_FC) sF[i >> 6][i & 63] = fcW[i];
    }
    if (threadIdx.x < D) {
        sb[threadIdx.x]  = bias[threadIdx.x];
        sg[threadIdx.x]  = gamma[threadIdx.x];
        sbt[threadIdx.x] = beta[threadIdx.x];
        if (FUSE_FC) sfb[threadIdx.x] = fcb[threadIdx.x];
    }
    __syncthreads();

    const int warp = threadIdx.x >> 5;
    const int lane = threadIdx.x & 31;
    const int f8      = lane & 7;    // which 16B (8-bf16) chunk of the 128B row
    const int quarter = lane >> 3;   // which of 4 concurrent edges
    const int warps_per_grid = (blockDim.x >> 5) * gridDim.x;

    for (int r = blockIdx.x * (blockDim.x >> 5) + warp; r < N; r += warps_per_grid) {
        const int start = __ldg(g_offs + r);
        const int end   = __ldg(g_offs + r + 1);

        float acc [8] = {0.f, 0.f, 0.f, 0.f, 0.f, 0.f, 0.f, 0.f};
        float acc2[8] = {0.f, 0.f, 0.f, 0.f, 0.f, 0.f, 0.f, 0.f};
        float cw = 0.f, cw2 = 0.f;

        int i = start + quarter;
        // 2 edges in flight per quarter (8 warp-wide)
        for (; i + 4 < end; i += 8) {
            float4 r0 = __ldg(g_edges + i);
            float4 r1 = __ldg(g_edges + i + 4);
            float w0 = (L == 0) ? r0.y : (L == 1) ? r0.z : r0.w;
            float w1 = (L == 0) ? r1.y : (L == 1) ? r1.z : r1.w;
            uint4 u0 = __ldg((const uint4*)(hin_b + (size_t)__float_as_int(r0.x) * D) + f8);
            uint4 u1 = __ldg((const uint4*)(hin_b + (size_t)__float_as_int(r1.x) * D) + f8);
            cvt_fma8(acc,  u0, w0); cw  += w0;
            cvt_fma8(acc2, u1, w1); cw2 += w1;
        }
        for (; i < end; i += 4) {
            float4 re = __ldg(g_edges + i);
            float we = (L == 0) ? re.y : (L == 1) ? re.z : re.w;
            uint4 u = __ldg((const uint4*)(hin_b + (size_t)__float_as_int(re.x) * D) + f8);
            cvt_fma8(acc, u, we); cw += we;
        }
#pragma unroll
        for (int j = 0; j < 8; j++) acc[j] += acc2[j];
        cw += cw2;

        // reduce over the 4 quarters (lane bits 3,4)
#pragma unroll
        for (int j = 0; j < 8; j++) {
            acc[j] += __shfl_xor_sync(0xffffffffu, acc[j], 8);
            acc[j] += __shfl_xor_sync(0xffffffffu, acc[j], 16);
        }
        // c = sum w; each edge's w counted by its 8 lanes -> exact /8
#pragma unroll
        for (int o = 16; o > 0; o >>= 1)
            cw += __shfl_xor_sync(0xffffffffu, cw, o);
        cw *= (1.f / 8.f);

        if (lane < 8) {
#pragma unroll
            for (int j = 0; j < 8; j++)
                sA[warp][f8 * 8 + j] = acc[j];
        }
        __syncwarp();

        float hi0 = hin[(size_t)r * D + lane];
        float hi1 = hin[(size_t)r * D + lane + 32];

        float a0 = sA[warp][lane]      - cw * hi0;
        float a1 = sA[warp][lane + 32] - cw * hi1;
        __syncwarp();

        float acc0 = 0.f, acc1 = 0.f;
#pragma unroll
        for (int k = 0; k < 32; k++) {
            float ak = __shfl_sync(0xffffffffu, a0, k);
            acc0 = fmaf(ak, sW[lane][k], acc0);
            acc1 = fmaf(ak, sW[lane + 32][k], acc1);
        }
#pragma unroll
        for (int k = 0; k < 32; k++) {
            float ak = __shfl_sync(0xffffffffu, a1, k);
            acc0 = fmaf(ak, sW[lane][k + 32], acc0);
            acc1 = fmaf(ak, sW[lane + 32][k + 32], acc1);
        }

        float h0 = fmaxf(acc0 + sb[lane], 0.f);
        float h1 = fmaxf(acc1 + sb[lane + 32], 0.f);

        float s2 = h0 + h1;
        float sq = h0 * h0 + h1 * h1;
#pragma unroll
        for (int o = 16; o > 0; o >>= 1) {
            s2 += __shfl_xor_sync(0xffffffffu, s2, o);
            sq += __shfl_xor_sync(0xffffffffu, sq, o);
        }
        float mu  = s2 * (1.f / D);
        float var = sq * (1.f / D) - mu * mu;
        float inv = rsqrtf(var + 1e-5f);

        float o0 = (h0 - mu) * inv * sg[lane]      + sbt[lane]      + hi0;
        float o1 = (h1 - mu) * inv * sg[lane + 32] + sbt[lane + 32] + hi1;

        if (FUSE_FC) {
            float f0 = 0.f, f1 = 0.f;
#pragma unroll
            for (int k = 0; k < 32; k++) {
                float hk = __shfl_sync(0xffffffffu, o0, k);
                f0 = fmaf(hk, sF[lane][k], f0);
                f1 = fmaf(hk, sF[lane + 32][k], f1);
            }
#pragma unroll
            for (int k = 0; k < 32; k++) {
                float hk = __shfl_sync(0xffffffffu, o1, k);
                f0 = fmaf(hk, sF[lane][k + 32], f0);
                f1 = fmaf(hk, sF[lane + 32][k + 32], f1);
            }
            hout[(size_t)r * D + lane]      = f0 + sfb[lane];
            hout[(size_t)r * D + lane + 32] = f1 + sfb[lane + 32];
        } else {
            hout[(size_t)r * D + lane]      = o0;
            hout[(size_t)r * D + lane + 32] = o1;
            hout_b[(size_t)r * D + lane]      = __float2bfloat16(o0);
            hout_b[(size_t)r * D + lane + 32] = __float2bfloat16(o1);
        }
    }
}

// ---------------------------------------------------------------------------
extern "C" void kernel_launch(void* const* d_in, const int* in_sizes, int n_in,
                              void* d_out, int out_size)
{
    const float* x      = (const float*)d_in[0];
    const void*  eidx   = d_in[1];
    const float* eattr  = (const float*)d_in[2];
    const float* lin_w  = (const float*)d_in[3];
    const float* lin_b  = (const float*)d_in[4];
    const float* emlp_w = (const float*)d_in[5];
    const float* emlp_b = (const float*)d_in[6];
    const float* gamma  = (const float*)d_in[7];
    const float* beta   = (const float*)d_in[8];
    const float* fc_w   = (const float*)d_in[9];
    const float* fc_b   = (const float*)d_in[10];
    float*       out    = (float*)d_out;

    const int E = in_sizes[1] / 2;
    const int N = in_sizes[0] / D;

    float *hA, *hB;
    __nv_bfloat16 *xb, *hbA, *hbB;
    cudaGetSymbolAddress((void**)&hA,  g_hA);
    cudaGetSymbolAddress((void**)&hB,  g_hB);
    cudaGetSymbolAddress((void**)&xb,  g_xb);
    cudaGetSymbolAddress((void**)&hbA, g_hbA);
    cudaGetSymbolAddress((void**)&hbB, g_hbB);

    // --- CSR build + edge weights + bf16 shadow of x ---
    const int NB = (N + SCAN_B - 1) / SCAN_B;
    detect_kernel<<<1, 256>>>((const int*)eidx);
    zero_deg_kernel<<<(N + 255) / 256, 256>>>(N);
    hist_kernel<<<(E + 255) / 256, 256>>>(eidx, E);
    scan_phase1<<<NB, SCAN_B>>>(N);
    scan_phase2<<<1, 1024>>>(NB);
    scan_phase3<<<NB, SCAN_B>>>(N);
    place_kernel<<<(E + 255) / 256, 256>>>(eidx, eattr, emlp_w, emlp_b, E);
    f2bf_kernel<<<(N * D / 4 + 255) / 256, 256>>>(x, xb, N * D);

    // --- layers (fused gather + GEMM + LN + residual) ---
    const int blocks = 2048, threads = 256;

    layer_kernel<0, false><<<blocks, threads>>>(x,  xb,  hA, hbA,
                                                lin_w, lin_b, gamma, beta,
                                                nullptr, nullptr, N);
    layer_kernel<1, false><<<blocks, threads>>>(hA, hbA, hB, hbB,
                                                lin_w + (size_t)D * D, lin_b + D,
                                                gamma + D, beta + D,
                                                nullptr, nullptr, N);
    layer_kernel<2, true><<<blocks, threads>>>(hB, hbB, out, nullptr,
                                               lin_w + (size_t)2 * D * D, lin_b + 2 * D,
                                               gamma + 2 * D, beta + 2 * D,
                                               fc_w, fc_b, N);
}

// round 9
// speedup vs baseline: 1.7656x; 1.0222x over previous
#include <cuda_runtime.h>
#include <cuda_bf16.h>
#include <math.h>

#define N_NODES_MAX 100000
#define N_EDGES_MAX 3200000
#define D 64
#define NL 3
#define SCAN_B 256
#define MAX_NB ((N_NODES_MAX + SCAN_B - 1) / SCAN_B + 1)

// ---- device scratch (no allocation allowed). 256B-aligned for vector loads. ----
// Edge record: .x = src id (bit-cast int), .y/.z/.w = softplus weight for layer 0/1/2
__device__ __align__(256) float4 g_edges[N_EDGES_MAX];
__device__ __align__(256) int   g_deg[N_NODES_MAX];
__device__ __align__(256) int   g_offs[N_NODES_MAX + 1];
__device__ __align__(256) int   g_cur[N_NODES_MAX];
__device__ __align__(256) int   g_bsum[MAX_NB];
__device__ __align__(256) int   g_boff[MAX_NB];
__device__ __align__(256) float g_hA[(size_t)N_NODES_MAX * D];
__device__ __align__(256) float g_hB[(size_t)N_NODES_MAX * D];
__device__ __align__(256) __nv_bfloat16 g_xb [(size_t)N_NODES_MAX * D];
__device__ __align__(256) __nv_bfloat16 g_hbA[(size_t)N_NODES_MAX * D];
__device__ __align__(256) __nv_bfloat16 g_hbB[(size_t)N_NODES_MAX * D];
__device__ int g_is64;

// ---------------------------------------------------------------------------
__global__ void detect_kernel(const int* __restrict__ w32)
{
    __shared__ int any;
    if (threadIdx.x == 0) any = 0;
    __syncthreads();
    int acc = 0;
    for (int i = threadIdx.x * 2 + 1; i < 4096; i += blockDim.x * 2)
        acc |= w32[i];
    if (acc) atomicOr(&any, 1);
    __syncthreads();
    if (threadIdx.x == 0) g_is64 = (any == 0) ? 1 : 0;
}

__global__ void zero_deg_kernel(int n)
{
    int i = blockIdx.x * blockDim.x + threadIdx.x;
    if (i < n) g_deg[i] = 0;
}

__global__ void hist_kernel(const void* __restrict__ eidx_raw, int E)
{
    int e = blockIdx.x * blockDim.x + threadIdx.x;
    if (e >= E) return;
    int d;
    if (g_is64) d = (int)((const long long*)eidx_raw)[(size_t)E + e];
    else        d = ((const int*)eidx_raw)[(size_t)E + e];
    atomicAdd(&g_deg[d], 1);
}

__global__ void scan_phase1(int N)
{
    __shared__ int sh[SCAN_B];
    const int tid = threadIdx.x;
    const int i = blockIdx.x * SCAN_B + tid;
    int v = (i < N) ? g_deg[i] : 0;
    sh[tid] = v;
    __syncthreads();
    for (int off = 1; off < SCAN_B; off <<= 1) {
        int a = sh[tid];
        int b = (tid >= off) ? sh[tid - off] : 0;
        __syncthreads();
        sh[tid] = a + b;
        __syncthreads();
    }
    if (i < N) g_offs[i] = sh[tid] - v;
    if (tid == SCAN_B - 1) g_bsum[blockIdx.x] = sh[SCAN_B - 1];
}

__global__ void scan_phase2(int NB)
{
    __shared__ int sh[1024];
    const int tid = threadIdx.x;
    int v = (tid < NB) ? g_bsum[tid] : 0;
    sh[tid] = v;
    __syncthreads();
    for (int off = 1; off < 1024; off <<= 1) {
        int a = sh[tid];
        int b = (tid >= off) ? sh[tid - off] : 0;
        __syncthreads();
        sh[tid] = a + b;
        __syncthreads();
    }
    if (tid < NB) g_boff[tid] = sh[tid] - v;
}

__global__ void scan_phase3(int N)
{
    const int i = blockIdx.x * SCAN_B + threadIdx.x;
    if (i < N) {
        int o = g_offs[i] + g_boff[blockIdx.x];
        g_offs[i] = o;
        g_cur[i]  = o;
        if (i == N - 1) g_offs[N] = o + g_deg[i];
    }
}

__global__ void place_kernel(const void* __restrict__ eidx_raw,
                             const float* __restrict__ eattr,
                             const float* __restrict__ emlp_w,
                             const float* __restrict__ emlp_b,
                             int E)
{
    int e = blockIdx.x * blockDim.x + threadIdx.x;
    if (e >= E) return;

    int s, d;
    if (g_is64) {
        const long long* p = (const long long*)eidx_raw;
        s = (int)p[e];
        d = (int)p[(size_t)E + e];
    } else {
        const int* p = (const int*)eidx_raw;
        s = p[e];
        d = p[(size_t)E + e];
    }

    const float4 a0 = *(const float4*)(eattr + (size_t)e * 8);
    const float4 a1 = *(const float4*)(eattr + (size_t)e * 8 + 4);

    float sp[NL];
#pragma unroll
    for (int l = 0; l < NL; l++) {
        const float* wp = emlp_w + l * 8;
        float z = emlp_b[l];
        z = fmaf(a0.x, wp[0], z);
        z = fmaf(a0.y, wp[1], z);
        z = fmaf(a0.z, wp[2], z);
        z = fmaf(a0.w, wp[3], z);
        z = fmaf(a1.x, wp[4], z);
        z = fmaf(a1.y, wp[5], z);
        z = fmaf(a1.z, wp[6], z);
        z = fmaf(a1.w, wp[7], z);
        sp[l] = fmaxf(z, 0.f) + log1pf(expf(-fabsf(z)));
    }

    int pos = atomicAdd(&g_cur[d], 1);
    g_edges[pos] = make_float4(__int_as_float(s), sp[0], sp[1], sp[2]);
}

// ---------------------------------------------------------------------------
__global__ void f2bf_kernel(const float* __restrict__ in,
                            __nv_bfloat16* __restrict__ out, int n)
{
    int idx = (blockIdx.x * blockDim.x + threadIdx.x) * 4;
    if (idx < n) {
        float4 v = *(const float4*)(in + idx);
        *(__nv_bfloat162*)(out + idx)     = __floats2bfloat162_rn(v.x, v.y);
        *(__nv_bfloat162*)(out + idx + 2) = __floats2bfloat162_rn(v.z, v.w);
    }
}

// ---------------------------------------------------------------------------
__device__ __forceinline__ void cvt_fma8(float* acc, uint4 u, float w)
{
    float2 p;
    p = __bfloat1622float2(*reinterpret_cast<__nv_bfloat162*>(&u.x));
    acc[0] = fmaf(w, p.x, acc[0]); acc[1] = fmaf(w, p.y, acc[1]);
    p = __bfloat1622float2(*reinterpret_cast<__nv_bfloat162*>(&u.y));
    acc[2] = fmaf(w, p.x, acc[2]); acc[3] = fmaf(w, p.y, acc[3]);
    p = __bfloat1622float2(*reinterpret_cast<__nv_bfloat162*>(&u.z));
    acc[4] = fmaf(w, p.x, acc[4]); acc[5] = fmaf(w, p.y, acc[5]);
    p = __bfloat1622float2(*reinterpret_cast<__nv_bfloat162*>(&u.w));
    acc[6] = fmaf(w, p.x, acc[6]); acc[7] = fmaf(w, p.y, acc[7]);
}

// ---------------------------------------------------------------------------
// Fused per-layer kernel. Warp per node r. Gather phase batches 16 edges per
// warp pass: each 8-lane quarter keeps 4 edge records + 4 bf16 row gathers
// in flight (MLP=4) before any FMA.
// ---------------------------------------------------------------------------
template <int L, bool FUSE_FC>
__global__ void __launch_bounds__(256)
layer_kernel(const float* __restrict__ hin,
             const __nv_bfloat16* __restrict__ hin_b,
             float* __restrict__ hout,
             __nv_bfloat16* __restrict__ hout_b,   // may be null
             const float* __restrict__ W,
             const float* __restrict__ bias,
             const float* __restrict__ gamma,
             const float* __restrict__ beta,
             const float* __restrict__ fcW,
             const float* __restrict__ fcb,
             int N)
{
    __shared__ float sW[D][D + 1];
    __shared__ float sF[FUSE_FC ? D : 1][FUSE_FC ? (D + 1) : 1];
    __shared__ float sb[D], sg[D], sbt[D], sfb[D];
    __shared__ float sA[8][D];   // 8 warps per block

    for (int i = threadIdx.x; i < D * D; i += blockDim.x) {
        sW[i >> 6][i & 63] = W[i];
        if (FUSE_FC) sF[i >> 6][i & 63] = fcW[i];
    }
    if (threadIdx.x < D) {
        sb[threadIdx.x]  = bias[threadIdx.x];
        sg[threadIdx.x]  = gamma[threadIdx.x];
        sbt[threadIdx.x] = beta[threadIdx.x];
        if (FUSE_FC) sfb[threadIdx.x] = fcb[threadIdx.x];
    }
    __syncthreads();

    const int warp = threadIdx.x >> 5;
    const int lane = threadIdx.x & 31;
    const int f8      = lane & 7;    // which 16B (8-bf16) chunk of the 128B row
    const int quarter = lane >> 3;   // which of 4 concurrent edges
    const int warps_per_grid = (blockDim.x >> 5) * gridDim.x;

    for (int r = blockIdx.x * (blockDim.x >> 5) + warp; r < N; r += warps_per_grid) {
        const int start = __ldg(g_offs + r);
        const int end   = __ldg(g_offs + r + 1);

        float acc [8] = {0.f, 0.f, 0.f, 0.f, 0.f, 0.f, 0.f, 0.f};
        float acc2[8] = {0.f, 0.f, 0.f, 0.f, 0.f, 0.f, 0.f, 0.f};
        float cw = 0.f, cw2 = 0.f;

        int i = start + quarter;
        // 4 edges in flight per quarter (16 per warp pass)
        for (; i + 12 < end; i += 16) {
            float4 r0 = __ldg(g_edges + i);
            float4 r1 = __ldg(g_edges + i + 4);
            float4 r2 = __ldg(g_edges + i + 8);
            float4 r3 = __ldg(g_edges + i + 12);
            uint4 u0 = __ldg((const uint4*)(hin_b + (size_t)__float_as_int(r0.x) * D) + f8);
            uint4 u1 = __ldg((const uint4*)(hin_b + (size_t)__float_as_int(r1.x) * D) + f8);
            uint4 u2 = __ldg((const uint4*)(hin_b + (size_t)__float_as_int(r2.x) * D) + f8);
            uint4 u3 = __ldg((const uint4*)(hin_b + (size_t)__float_as_int(r3.x) * D) + f8);
            float w0 = (L == 0) ? r0.y : (L == 1) ? r0.z : r0.w;
            float w1 = (L == 0) ? r1.y : (L == 1) ? r1.z : r1.w;
            float w2 = (L == 0) ? r2.y : (L == 1) ? r2.z : r2.w;
            float w3 = (L == 0) ? r3.y : (L == 1) ? r3.z : r3.w;
            cvt_fma8(acc,  u0, w0); cw  += w0;
            cvt_fma8(acc2, u1, w1); cw2 += w1;
            cvt_fma8(acc,  u2, w2); cw  += w2;
            cvt_fma8(acc2, u3, w3); cw2 += w3;
        }
        for (; i < end; i += 4) {
            float4 re = __ldg(g_edges + i);
            float we = (L == 0) ? re.y : (L == 1) ? re.z : re.w;
            uint4 u = __ldg((const uint4*)(hin_b + (size_t)__float_as_int(re.x) * D) + f8);
            cvt_fma8(acc, u, we); cw += we;
        }
#pragma unroll
        for (int j = 0; j < 8; j++) acc[j] += acc2[j];
        cw += cw2;

        // reduce over the 4 quarters (lane bits 3,4)
#pragma unroll
        for (int j = 0; j < 8; j++) {
            acc[j] += __shfl_xor_sync(0xffffffffu, acc[j], 8);
            acc[j] += __shfl_xor_sync(0xffffffffu, acc[j], 16);
        }
        // c = sum w; each edge's w counted by its 8 lanes -> exact /8
#pragma unroll
        for (int o = 16; o > 0; o >>= 1)
            cw += __shfl_xor_sync(0xffffffffu, cw, o);
        cw *= (1.f / 8.f);

        if (lane < 8) {
#pragma unroll
            for (int j = 0; j < 8; j++)
                sA[warp][f8 * 8 + j] = acc[j];
        }
        __syncwarp();

        float hi0 = hin[(size_t)r * D + lane];
        float hi1 = hin[(size_t)r * D + lane + 32];

        float a0 = sA[warp][lane]      - cw * hi0;
        float a1 = sA[warp][lane + 32] - cw * hi1;
        __syncwarp();

        float acc0 = 0.f, acc1 = 0.f;
#pragma unroll
        for (int k = 0; k < 32; k++) {
            float ak = __shfl_sync(0xffffffffu, a0, k);
            acc0 = fmaf(ak, sW[lane][k], acc0);
            acc1 = fmaf(ak, sW[lane + 32][k], acc1);
        }
#pragma unroll
        for (int k = 0; k < 32; k++) {
            float ak = __shfl_sync(0xffffffffu, a1, k);
            acc0 = fmaf(ak, sW[lane][k + 32], acc0);
            acc1 = fmaf(ak, sW[lane + 32][k + 32], acc1);
        }

        float h0 = fmaxf(acc0 + sb[lane], 0.f);
        float h1 = fmaxf(acc1 + sb[lane + 32], 0.f);

        float s2 = h0 + h1;
        float sq = h0 * h0 + h1 * h1;
#pragma unroll
        for (int o = 16; o > 0; o >>= 1) {
            s2 += __shfl_xor_sync(0xffffffffu, s2, o);
            sq += __shfl_xor_sync(0xffffffffu, sq, o);
        }
        float mu  = s2 * (1.f / D);
        float var = sq * (1.f / D) - mu * mu;
        float inv = rsqrtf(var + 1e-5f);

        float o0 = (h0 - mu) * inv * sg[lane]      + sbt[lane]      + hi0;
        float o1 = (h1 - mu) * inv * sg[lane + 32] + sbt[lane + 32] + hi1;

        if (FUSE_FC) {
            float f0 = 0.f, f1 = 0.f;
#pragma unroll
            for (int k = 0; k < 32; k++) {
                float hk = __shfl_sync(0xffffffffu, o0, k);
                f0 = fmaf(hk, sF[lane][k], f0);
                f1 = fmaf(hk, sF[lane + 32][k], f1);
            }
#pragma unroll
            for (int k = 0; k < 32; k++) {
                float hk = __shfl_sync(0xffffffffu, o1, k);
                f0 = fmaf(hk, sF[lane][k + 32], f0);
                f1 = fmaf(hk, sF[lane + 32][k + 32], f1);
            }
            hout[(size_t)r * D + lane]      = f0 + sfb[lane];
            hout[(size_t)r * D + lane + 32] = f1 + sfb[lane + 32];
        } else {
            hout[(size_t)r * D + lane]      = o0;
            hout[(size_t)r * D + lane + 32] = o1;
            hout_b[(size_t)r * D + lane]      = __float2bfloat16(o0);
            hout_b[(size_t)r * D + lane + 32] = __float2bfloat16(o1);
        }
    }
}

// ---------------------------------------------------------------------------
extern "C" void kernel_launch(void* const* d_in, const int* in_sizes, int n_in,
                              void* d_out, int out_size)
{
    const float* x      = (const float*)d_in[0];
    const void*  eidx   = d_in[1];
    const float* eattr  = (const float*)d_in[2];
    const float* lin_w  = (const float*)d_in[3];
    const float* lin_b  = (const float*)d_in[4];
    const float* emlp_w = (const float*)d_in[5];
    const float* emlp_b = (const float*)d_in[6];
    const float* gamma  = (const float*)d_in[7];
    const float* beta   = (const float*)d_in[8];
    const float* fc_w   = (const float*)d_in[9];
    const float* fc_b   = (const float*)d_in[10];
    float*       out    = (float*)d_out;

    const int E = in_sizes[1] / 2;
    const int N = in_sizes[0] / D;

    float *hA, *hB;
    __nv_bfloat16 *xb, *hbA, *hbB;
    cudaGetSymbolAddress((void**)&hA,  g_hA);
    cudaGetSymbolAddress((void**)&hB,  g_hB);
    cudaGetSymbolAddress((void**)&xb,  g_xb);
    cudaGetSymbolAddress((void**)&hbA, g_hbA);
    cudaGetSymbolAddress((void**)&hbB, g_hbB);

    // --- CSR build + edge weights + bf16 shadow of x ---
    const int NB = (N + SCAN_B - 1) / SCAN_B;
    detect_kernel<<<1, 256>>>((const int*)eidx);
    zero_deg_kernel<<<(N + 255) / 256, 256>>>(N);
    hist_kernel<<<(E + 255) / 256, 256>>>(eidx, E);
    scan_phase1<<<NB, SCAN_B>>>(N);
    scan_phase2<<<1, 1024>>>(NB);
    scan_phase3<<<NB, SCAN_B>>>(N);
    place_kernel<<<(E + 255) / 256, 256>>>(eidx, eattr, emlp_w, emlp_b, E);
    f2bf_kernel<<<(N * D / 4 + 255) / 256, 256>>>(x, xb, N * D);

    // --- layers (fused gather + GEMM + LN + residual) ---
    const int blocks = 2960, threads = 256;

    layer_kernel<0, false><<<blocks, threads>>>(x,  xb,  hA, hbA,
                                                lin_w, lin_b, gamma, beta,
                                                nullptr, nullptr, N);
    layer_kernel<1, false><<<blocks, threads>>>(hA, hbA, hB, hbB,
                                                lin_w + (size_t)D * D, lin_b + D,
                                                gamma + D, beta + D,
                                                nullptr, nullptr, N);
    layer_kernel<2, true><<<blocks, threads>>>(hB, hbB, out, nullptr,
                                               lin_w + (size_t)2 * D * D, lin_b + 2 * D,
                                               gamma + 2 * D, beta + 2 * D,
                                               fc_w, fc_b, N);
}